// round 1
// baseline (speedup 1.0000x reference)
#include <cuda_runtime.h>

#define BATCH 8
#define SEQ   1024
#define HID   1024
#define NH    16
#define HD    64
#define MTOT  (BATCH*SEQ)   // 8192

// Scratch for projected Q/K/V in [B, nh, S, hd] layout (96 MB total, static — no allocs).
__device__ float g_q[(size_t)MTOT * HID];
__device__ float g_k[(size_t)MTOT * HID];
__device__ float g_v[(size_t)MTOT * HID];

// ---------------------------------------------------------------------------
// Fused QKV projection: C = X @ W + b for W in {Wq, Wk, Wv} (blockIdx.z picks)
// Classic SGEMM: BM=128, BN=128, BK=16, 256 threads, 8x8 register micro-tile.
// Output written directly in [B, nh, S, hd] layout.
// ---------------------------------------------------------------------------
#define BM 128
#define BN 128
#define BK 16

__global__ __launch_bounds__(256) void qkv_gemm(
    const float* __restrict__ X,
    const float* __restrict__ Wq, const float* __restrict__ bq,
    const float* __restrict__ Wk, const float* __restrict__ bk,
    const float* __restrict__ Wv, const float* __restrict__ bv)
{
    const float* W; const float* bias; float* out;
    if (blockIdx.z == 0)      { W = Wq; bias = bq; out = g_q; }
    else if (blockIdx.z == 1) { W = Wk; bias = bk; out = g_k; }
    else                      { W = Wv; bias = bv; out = g_v; }

    __shared__ __align__(16) float As[BK][BM];   // A stored transposed: As[k][m]
    __shared__ __align__(16) float Bs[BK][BN];

    const int tid  = threadIdx.x;          // 0..255
    const int row0 = blockIdx.y * BM;
    const int col0 = blockIdx.x * BN;
    const int tr   = tid >> 4;             // 0..15  (row group)
    const int tc   = tid & 15;             // 0..15  (col group)

    float acc[8][8];
    #pragma unroll
    for (int i = 0; i < 8; i++)
        #pragma unroll
        for (int j = 0; j < 8; j++) acc[i][j] = 0.0f;

    for (int k0 = 0; k0 < HID; k0 += BK) {
        // --- load tiles (A: 128x16 transposed into As, B: 16x128 straight) ---
        #pragma unroll
        for (int ph = 0; ph < 2; ph++) {
            int f4   = tid + ph * 256;                 // 0..511 float4 slots
            int arow = f4 >> 2;                        // 0..127
            int ak   = (f4 & 3) * 4;                   // 0,4,8,12
            float4 av = *(const float4*)(X + (size_t)(row0 + arow) * HID + k0 + ak);
            As[ak + 0][arow] = av.x;
            As[ak + 1][arow] = av.y;
            As[ak + 2][arow] = av.z;
            As[ak + 3][arow] = av.w;

            int brow = f4 >> 5;                        // 0..15
            int bc   = (f4 & 31) * 4;                  // 0..124
            *(float4*)&Bs[brow][bc] =
                *(const float4*)(W + (size_t)(k0 + brow) * HID + col0 + bc);
        }
        __syncthreads();

        // --- compute ---
        #pragma unroll
        for (int kk = 0; kk < BK; kk++) {
            float a[8], b[8];
            *(float4*)&a[0] = *(const float4*)&As[kk][tr * 8];
            *(float4*)&a[4] = *(const float4*)&As[kk][tr * 8 + 4];
            *(float4*)&b[0] = *(const float4*)&Bs[kk][tc * 8];
            *(float4*)&b[4] = *(const float4*)&Bs[kk][tc * 8 + 4];
            #pragma unroll
            for (int i = 0; i < 8; i++)
                #pragma unroll
                for (int j = 0; j < 8; j++)
                    acc[i][j] = fmaf(a[i], b[j], acc[i][j]);
        }
        __syncthreads();
    }

    // --- epilogue: add bias, scatter into [B, nh, S, hd] ---
    #pragma unroll
    for (int i = 0; i < 8; i++) {
        int row = row0 + tr * 8 + i;
        int bb  = row >> 10;
        int s   = row & (SEQ - 1);
        #pragma unroll
        for (int j = 0; j < 8; j++) {
            int col = col0 + tc * 8 + j;
            int h   = col >> 6;
            int d   = col & (HD - 1);
            out[(((size_t)bb * NH + h) * SEQ + s) * HD + d] = acc[i][j] + bias[col];
        }
    }
}

// ---------------------------------------------------------------------------
// Attention with constituency penalty.
// Grid: (S/128 q-tiles, NH, B). Block: 128 threads, one thread per q row.
// q row + output accumulator live in registers; K/V tiles (64x64, aligned to
// constituent blocks so the penalty is a per-tile scalar) staged in smem.
// Max-free softmax: scores are O(+-6) by construction, exp() cannot overflow.
// ---------------------------------------------------------------------------
__global__ __launch_bounds__(128) void attn_kernel(float* __restrict__ out)
{
    const int qt = blockIdx.x;     // 0..7
    const int h  = blockIdx.y;     // 0..15
    const int bb = blockIdx.z;     // 0..7
    const int t  = threadIdx.x;    // 0..127
    const int qrow = qt * 128 + t;

    const size_t bh = (size_t)bb * NH + h;
    const float* qp = g_q + (bh * SEQ + qrow) * HD;
    const float* kb = g_k + bh * SEQ * HD;
    const float* vb = g_v + bh * SEQ * HD;

    __shared__ __align__(16) float Ks[64][HD];
    __shared__ __align__(16) float Vs[64][HD];

    float qr[HD];
    #pragma unroll
    for (int d = 0; d < HD; d += 4)
        *(float4*)&qr[d] = *(const float4*)(qp + d);

    float o[HD];
    #pragma unroll
    for (int d = 0; d < HD; d++) o[d] = 0.0f;
    float l = 0.0f;

    const int qblk = qrow >> 6;

    for (int kt = 0; kt < SEQ / 64; kt++) {
        __syncthreads();
        const float4* kg  = (const float4*)(kb + (size_t)kt * 64 * HD);
        const float4* vg  = (const float4*)(vb + (size_t)kt * 64 * HD);
        float4* ksm = (float4*)Ks;
        float4* vsm = (float4*)Vs;
        #pragma unroll
        for (int i = 0; i < 8; i++) {
            int idx = t + i * 128;   // 1024 float4 per tile
            ksm[idx] = kg[idx];
            vsm[idx] = vg[idx];
        }
        __syncthreads();

        const float pen = (qblk != kt) ? 0.5f : 0.0f;

        #pragma unroll 4
        for (int j = 0; j < 64; j++) {
            // score = (q . k_j)/8 - pen   (4 independent FMA chains for ILP)
            float s0 = 0.f, s1 = 0.f, s2 = 0.f, s3 = 0.f;
            #pragma unroll
            for (int d = 0; d < HD; d += 4) {
                float4 kv = *(const float4*)&Ks[j][d];   // warp-broadcast LDS
                s0 = fmaf(qr[d],     kv.x, s0);
                s1 = fmaf(qr[d + 1], kv.y, s1);
                s2 = fmaf(qr[d + 2], kv.z, s2);
                s3 = fmaf(qr[d + 3], kv.w, s3);
            }
            float s = ((s0 + s1) + (s2 + s3)) * 0.125f - pen;
            float p = __expf(s);
            l += p;
            #pragma unroll
            for (int d = 0; d < HD; d += 4) {
                float4 vv = *(const float4*)&Vs[j][d];   // warp-broadcast LDS
                o[d]     = fmaf(p, vv.x, o[d]);
                o[d + 1] = fmaf(p, vv.y, o[d + 1]);
                o[d + 2] = fmaf(p, vv.z, o[d + 2]);
                o[d + 3] = fmaf(p, vv.w, o[d + 3]);
            }
        }
    }

    const float inv = 1.0f / l;
    float* op = out + ((size_t)bb * SEQ + qrow) * HID + h * HD;
    #pragma unroll
    for (int d = 0; d < HD; d += 4) {
        float4 r;
        r.x = o[d]     * inv;
        r.y = o[d + 1] * inv;
        r.z = o[d + 2] * inv;
        r.w = o[d + 3] * inv;
        *(float4*)(op + d) = r;
    }
}

// ---------------------------------------------------------------------------
extern "C" void kernel_launch(void* const* d_in, const int* in_sizes, int n_in,
                              void* d_out, int out_size)
{
    const float* X  = (const float*)d_in[0];
    const float* Wq = (const float*)d_in[1];
    const float* bq = (const float*)d_in[2];
    const float* Wk = (const float*)d_in[3];
    const float* bk = (const float*)d_in[4];
    const float* Wv = (const float*)d_in[5];
    const float* bv = (const float*)d_in[6];

    dim3 g1(HID / BN, MTOT / BM, 3);    // (8, 64, 3) = 1536 CTAs
    qkv_gemm<<<g1, 256>>>(X, Wq, bq, Wk, bk, Wv, bv);

    dim3 g2(SEQ / 128, NH, BATCH);      // (8, 16, 8) = 1024 CTAs
    attn_kernel<<<g2, 128>>>((float*)d_out);
}

// round 2
// speedup vs baseline: 1.3847x; 1.3847x over previous
#include <cuda_runtime.h>
#include <cstdint>

#define BATCH 8
#define SEQ   1024
#define HID   1024
#define NH    16
#define HD    64
#define MTOT  (BATCH*SEQ)   // 8192

// Scratch for projected Q/K/V in [B, nh, S, hd] layout (96 MB, static).
__device__ float g_q[(size_t)MTOT * HID];
__device__ float g_k[(size_t)MTOT * HID];
__device__ float g_v[(size_t)MTOT * HID];

// ---------------------------------------------------------------------------
// TF32 tensor-core QKV projection: C = X @ W + b  (blockIdx.z picks Wq/Wk/Wv)
// BM=128, BN=128, BK=32, 256 threads (8 warps, 2x4), warp tile 64x32,
// mma.sync.m16n8k8.tf32. Register-prefetch double buffering for gmem.
// Smem pads: As stride 36 / Bs stride 136 -> all fragment LDS conflict-free.
// ---------------------------------------------------------------------------
#define BM 128
#define BN 128
#define BK 32
#define APAD 36    // As row stride in floats
#define BPAD 136   // Bs row stride in floats

__device__ __forceinline__ uint32_t f2tf32(float f) {
    uint32_t u;
    asm("cvt.rna.tf32.f32 %0, %1;" : "=r"(u) : "f"(f));
    return u;
}

__device__ __forceinline__ void mma_tf32(float c[4], const uint32_t a[4],
                                         const uint32_t b[2]) {
    asm volatile(
        "mma.sync.aligned.m16n8k8.row.col.f32.tf32.tf32.f32 "
        "{%0,%1,%2,%3}, {%4,%5,%6,%7}, {%8,%9}, {%0,%1,%2,%3};\n"
        : "+f"(c[0]), "+f"(c[1]), "+f"(c[2]), "+f"(c[3])
        : "r"(a[0]), "r"(a[1]), "r"(a[2]), "r"(a[3]), "r"(b[0]), "r"(b[1]));
}

__global__ __launch_bounds__(256, 1) void qkv_gemm_tf32(
    const float* __restrict__ X,
    const float* __restrict__ Wq, const float* __restrict__ bq,
    const float* __restrict__ Wk, const float* __restrict__ bk,
    const float* __restrict__ Wv, const float* __restrict__ bv)
{
    const float* W; const float* bias; float* out;
    if (blockIdx.z == 0)      { W = Wq; bias = bq; out = g_q; }
    else if (blockIdx.z == 1) { W = Wk; bias = bk; out = g_k; }
    else                      { W = Wv; bias = bv; out = g_v; }

    __shared__ __align__(16) uint32_t As[BM * APAD];   // 18.4 KB
    __shared__ __align__(16) uint32_t Bs[BK * BPAD];   // 17.4 KB

    const int tid  = threadIdx.x;
    const int lane = tid & 31;
    const int w    = tid >> 5;
    const int wm   = w >> 2;            // 0..1  (m warp coord)
    const int wn   = w & 3;             // 0..3  (n warp coord)
    const int m0   = blockIdx.y * BM;
    const int n0   = blockIdx.x * BN;

    const int lg   = lane >> 2;         // groupID 0..7
    const int lt   = lane & 3;          // thread-in-group 0..3

    float c[4][4][4];
    #pragma unroll
    for (int mt = 0; mt < 4; mt++)
        #pragma unroll
        for (int nt = 0; nt < 4; nt++)
            #pragma unroll
            for (int i = 0; i < 4; i++) c[mt][nt][i] = 0.0f;

    // Per-thread gmem tile slices (4 float4 of A, 4 of B per iteration)
    uint4 pa[4], pb[4];

    // indices are compile-time derivable from tid: precompute
    int a_row[4], a_col[4], b_row[4], b_col[4];
    #pragma unroll
    for (int ph = 0; ph < 4; ph++) {
        int idx = tid + ph * 256;       // 0..1023
        a_row[ph] = idx >> 3;           // 0..127
        a_col[ph] = (idx & 7) * 4;      // 0..28
        b_row[ph] = idx >> 5;           // 0..31
        b_col[ph] = (idx & 31) * 4;     // 0..124
    }

    // ---- preamble: load k0=0 tile, convert to tf32, store to smem ----
    #pragma unroll
    for (int ph = 0; ph < 4; ph++) {
        float4 av = *(const float4*)(X + (size_t)(m0 + a_row[ph]) * HID + a_col[ph]);
        pa[ph] = make_uint4(f2tf32(av.x), f2tf32(av.y), f2tf32(av.z), f2tf32(av.w));
        float4 bv2 = *(const float4*)(W + (size_t)b_row[ph] * HID + n0 + b_col[ph]);
        pb[ph] = make_uint4(f2tf32(bv2.x), f2tf32(bv2.y), f2tf32(bv2.z), f2tf32(bv2.w));
    }
    #pragma unroll
    for (int ph = 0; ph < 4; ph++) {
        *(uint4*)&As[a_row[ph] * APAD + a_col[ph]] = pa[ph];
        *(uint4*)&Bs[b_row[ph] * BPAD + b_col[ph]] = pb[ph];
    }
    __syncthreads();

    const int am0 = wm * 64;
    const int bn0 = wn * 32;

    for (int k0 = 0; k0 < HID; k0 += BK) {
        const bool more = (k0 + BK) < HID;
        // prefetch next tile into registers
        if (more) {
            #pragma unroll
            for (int ph = 0; ph < 4; ph++) {
                float4 av = *(const float4*)(X + (size_t)(m0 + a_row[ph]) * HID + k0 + BK + a_col[ph]);
                pa[ph] = make_uint4(f2tf32(av.x), f2tf32(av.y), f2tf32(av.z), f2tf32(av.w));
                float4 bv2 = *(const float4*)(W + (size_t)(k0 + BK + b_row[ph]) * HID + n0 + b_col[ph]);
                pb[ph] = make_uint4(f2tf32(bv2.x), f2tf32(bv2.y), f2tf32(bv2.z), f2tf32(bv2.w));
            }
        }

        // ---- compute BK=32 (4 k-tiles of 8) ----
        #pragma unroll
        for (int kt = 0; kt < 4; kt++) {
            const int kb = kt * 8;
            uint32_t af[4][4], bf[4][2];
            #pragma unroll
            for (int mt = 0; mt < 4; mt++) {
                int r = am0 + mt * 16 + lg;
                int cc = kb + lt;
                af[mt][0] = As[r * APAD + cc];
                af[mt][1] = As[(r + 8) * APAD + cc];
                af[mt][2] = As[r * APAD + cc + 4];
                af[mt][3] = As[(r + 8) * APAD + cc + 4];
            }
            #pragma unroll
            for (int nt = 0; nt < 4; nt++) {
                int nn = bn0 + nt * 8 + lg;
                int kk = kb + lt;
                bf[nt][0] = Bs[kk * BPAD + nn];
                bf[nt][1] = Bs[(kk + 4) * BPAD + nn];
            }
            #pragma unroll
            for (int mt = 0; mt < 4; mt++)
                #pragma unroll
                for (int nt = 0; nt < 4; nt++)
                    mma_tf32(c[mt][nt], af[mt], bf[nt]);
        }

        __syncthreads();
        if (more) {
            #pragma unroll
            for (int ph = 0; ph < 4; ph++) {
                *(uint4*)&As[a_row[ph] * APAD + a_col[ph]] = pa[ph];
                *(uint4*)&Bs[b_row[ph] * BPAD + b_col[ph]] = pb[ph];
            }
            __syncthreads();
        }
    }

    // ---- epilogue: bias add, scatter into [B, nh, S, hd] ----
    #pragma unroll
    for (int mt = 0; mt < 4; mt++) {
        int m = m0 + am0 + mt * 16 + lg;
        #pragma unroll
        for (int nt = 0; nt < 4; nt++) {
            int n = n0 + bn0 + nt * 8 + lt * 2;
            float b0 = bias[n], b1 = bias[n + 1];
            int h = n >> 6, d = n & (HD - 1);
            // row m (c0, c1)
            {
                int bb = m >> 10, s = m & (SEQ - 1);
                float2 r2 = make_float2(c[mt][nt][0] + b0, c[mt][nt][1] + b1);
                *(float2*)(out + (((size_t)bb * NH + h) * SEQ + s) * HD + d) = r2;
            }
            // row m+8 (c2, c3)
            {
                int m2 = m + 8;
                int bb = m2 >> 10, s = m2 & (SEQ - 1);
                float2 r2 = make_float2(c[mt][nt][2] + b0, c[mt][nt][3] + b1);
                *(float2*)(out + (((size_t)bb * NH + h) * SEQ + s) * HD + d) = r2;
            }
        }
    }
}

// ---------------------------------------------------------------------------
// Attention with constituency penalty (unchanged from R1 — near fp32 roofline;
// tensor-core conversion is the next round's change).
// ---------------------------------------------------------------------------
__global__ __launch_bounds__(128) void attn_kernel(float* __restrict__ out)
{
    const int qt = blockIdx.x;
    const int h  = blockIdx.y;
    const int bb = blockIdx.z;
    const int t  = threadIdx.x;
    const int qrow = qt * 128 + t;

    const size_t bh = (size_t)bb * NH + h;
    const float* qp = g_q + (bh * SEQ + qrow) * HD;
    const float* kb = g_k + bh * SEQ * HD;
    const float* vb = g_v + bh * SEQ * HD;

    __shared__ __align__(16) float Ks[64][HD];
    __shared__ __align__(16) float Vs[64][HD];

    float qr[HD];
    #pragma unroll
    for (int d = 0; d < HD; d += 4)
        *(float4*)&qr[d] = *(const float4*)(qp + d);

    float o[HD];
    #pragma unroll
    for (int d = 0; d < HD; d++) o[d] = 0.0f;
    float l = 0.0f;

    const int qblk = qrow >> 6;

    for (int kt = 0; kt < SEQ / 64; kt++) {
        __syncthreads();
        const float4* kg  = (const float4*)(kb + (size_t)kt * 64 * HD);
        const float4* vg  = (const float4*)(vb + (size_t)kt * 64 * HD);
        float4* ksm = (float4*)Ks;
        float4* vsm = (float4*)Vs;
        #pragma unroll
        for (int i = 0; i < 8; i++) {
            int idx = t + i * 128;
            ksm[idx] = kg[idx];
            vsm[idx] = vg[idx];
        }
        __syncthreads();

        const float pen = (qblk != kt) ? 0.5f : 0.0f;

        #pragma unroll 4
        for (int j = 0; j < 64; j++) {
            float s0 = 0.f, s1 = 0.f, s2 = 0.f, s3 = 0.f;
            #pragma unroll
            for (int d = 0; d < HD; d += 4) {
                float4 kv = *(const float4*)&Ks[j][d];
                s0 = fmaf(qr[d],     kv.x, s0);
                s1 = fmaf(qr[d + 1], kv.y, s1);
                s2 = fmaf(qr[d + 2], kv.z, s2);
                s3 = fmaf(qr[d + 3], kv.w, s3);
            }
            float s = ((s0 + s1) + (s2 + s3)) * 0.125f - pen;
            float p = __expf(s);
            l += p;
            #pragma unroll
            for (int d = 0; d < HD; d += 4) {
                float4 vv = *(const float4*)&Vs[j][d];
                o[d]     = fmaf(p, vv.x, o[d]);
                o[d + 1] = fmaf(p, vv.y, o[d + 1]);
                o[d + 2] = fmaf(p, vv.z, o[d + 2]);
                o[d + 3] = fmaf(p, vv.w, o[d + 3]);
            }
        }
    }

    const float inv = 1.0f / l;
    float* op = out + ((size_t)bb * SEQ + qrow) * HID + h * HD;
    #pragma unroll
    for (int d = 0; d < HD; d += 4) {
        float4 r;
        r.x = o[d]     * inv;
        r.y = o[d + 1] * inv;
        r.z = o[d + 2] * inv;
        r.w = o[d + 3] * inv;
        *(float4*)(op + d) = r;
    }
}

// ---------------------------------------------------------------------------
extern "C" void kernel_launch(void* const* d_in, const int* in_sizes, int n_in,
                              void* d_out, int out_size)
{
    const float* X  = (const float*)d_in[0];
    const float* Wq = (const float*)d_in[1];
    const float* bq = (const float*)d_in[2];
    const float* Wk = (const float*)d_in[3];
    const float* bk = (const float*)d_in[4];
    const float* Wv = (const float*)d_in[5];
    const float* bv = (const float*)d_in[6];

    dim3 g1(HID / BN, MTOT / BM, 3);    // (8, 64, 3) = 1536 CTAs
    qkv_gemm_tf32<<<g1, 256>>>(X, Wq, bq, Wk, bk, Wv, bv);

    dim3 g2(SEQ / 128, NH, BATCH);      // (8, 16, 8) = 1024 CTAs
    attn_kernel<<<g2, 128>>>((float*)d_out);
}

// round 4
// speedup vs baseline: 1.5909x; 1.1489x over previous
#include <cuda_runtime.h>
#include <cstdint>

#define BATCH 8
#define SEQ   1024
#define HID   1024
#define NH    16
#define HD    64
#define MTOT  (BATCH*SEQ)   // 8192

// Scratch for projected Q/K/V in [B, nh, S, hd] layout (96 MB, static).
__device__ float g_q[(size_t)MTOT * HID];
__device__ float g_k[(size_t)MTOT * HID];
__device__ float g_v[(size_t)MTOT * HID];

__device__ __forceinline__ uint32_t f2tf32(float f) {
    uint32_t u;
    asm("cvt.rna.tf32.f32 %0, %1;" : "=r"(u) : "f"(f));
    return u;
}

__device__ __forceinline__ float ex2(float x) {
    float r;
    asm("ex2.approx.ftz.f32 %0, %1;" : "=f"(r) : "f"(x));
    return r;
}

__device__ __forceinline__ void mma_tf32(float c[4], const uint32_t a[4],
                                         const uint32_t b[2]) {
    asm volatile(
        "mma.sync.aligned.m16n8k8.row.col.f32.tf32.tf32.f32 "
        "{%0,%1,%2,%3}, {%4,%5,%6,%7}, {%8,%9}, {%0,%1,%2,%3};\n"
        : "+f"(c[0]), "+f"(c[1]), "+f"(c[2]), "+f"(c[3])
        : "r"(a[0]), "r"(a[1]), "r"(a[2]), "r"(a[3]), "r"(b[0]), "r"(b[1]));
}

// ---------------------------------------------------------------------------
// TF32 tensor-core QKV projection (unchanged from R2 — passed at 4.9e-4).
// ---------------------------------------------------------------------------
#define BM 128
#define BN 128
#define BK 32
#define APAD 36
#define BPAD 136

__global__ __launch_bounds__(256, 1) void qkv_gemm_tf32(
    const float* __restrict__ X,
    const float* __restrict__ Wq, const float* __restrict__ bq,
    const float* __restrict__ Wk, const float* __restrict__ bk,
    const float* __restrict__ Wv, const float* __restrict__ bv)
{
    const float* W; const float* bias; float* out;
    if (blockIdx.z == 0)      { W = Wq; bias = bq; out = g_q; }
    else if (blockIdx.z == 1) { W = Wk; bias = bk; out = g_k; }
    else                      { W = Wv; bias = bv; out = g_v; }

    __shared__ __align__(16) uint32_t As[BM * APAD];
    __shared__ __align__(16) uint32_t Bs[BK * BPAD];

    const int tid  = threadIdx.x;
    const int lane = tid & 31;
    const int w    = tid >> 5;
    const int wm   = w >> 2;
    const int wn   = w & 3;
    const int m0   = blockIdx.y * BM;
    const int n0   = blockIdx.x * BN;
    const int lg   = lane >> 2;
    const int lt   = lane & 3;

    float c[4][4][4];
    #pragma unroll
    for (int mt = 0; mt < 4; mt++)
        #pragma unroll
        for (int nt = 0; nt < 4; nt++)
            #pragma unroll
            for (int i = 0; i < 4; i++) c[mt][nt][i] = 0.0f;

    uint4 pa[4], pb[4];
    int a_row[4], a_col[4], b_row[4], b_col[4];
    #pragma unroll
    for (int ph = 0; ph < 4; ph++) {
        int idx = tid + ph * 256;
        a_row[ph] = idx >> 3;
        a_col[ph] = (idx & 7) * 4;
        b_row[ph] = idx >> 5;
        b_col[ph] = (idx & 31) * 4;
    }

    #pragma unroll
    for (int ph = 0; ph < 4; ph++) {
        float4 av = *(const float4*)(X + (size_t)(m0 + a_row[ph]) * HID + a_col[ph]);
        pa[ph] = make_uint4(f2tf32(av.x), f2tf32(av.y), f2tf32(av.z), f2tf32(av.w));
        float4 bv2 = *(const float4*)(W + (size_t)b_row[ph] * HID + n0 + b_col[ph]);
        pb[ph] = make_uint4(f2tf32(bv2.x), f2tf32(bv2.y), f2tf32(bv2.z), f2tf32(bv2.w));
    }
    #pragma unroll
    for (int ph = 0; ph < 4; ph++) {
        *(uint4*)&As[a_row[ph] * APAD + a_col[ph]] = pa[ph];
        *(uint4*)&Bs[b_row[ph] * BPAD + b_col[ph]] = pb[ph];
    }
    __syncthreads();

    const int am0 = wm * 64;
    const int bn0 = wn * 32;

    for (int k0 = 0; k0 < HID; k0 += BK) {
        const bool more = (k0 + BK) < HID;
        if (more) {
            #pragma unroll
            for (int ph = 0; ph < 4; ph++) {
                float4 av = *(const float4*)(X + (size_t)(m0 + a_row[ph]) * HID + k0 + BK + a_col[ph]);
                pa[ph] = make_uint4(f2tf32(av.x), f2tf32(av.y), f2tf32(av.z), f2tf32(av.w));
                float4 bv2 = *(const float4*)(W + (size_t)(k0 + BK + b_row[ph]) * HID + n0 + b_col[ph]);
                pb[ph] = make_uint4(f2tf32(bv2.x), f2tf32(bv2.y), f2tf32(bv2.z), f2tf32(bv2.w));
            }
        }

        #pragma unroll
        for (int kt = 0; kt < 4; kt++) {
            const int kb = kt * 8;
            uint32_t af[4][4], bf[4][2];
            #pragma unroll
            for (int mt = 0; mt < 4; mt++) {
                int r = am0 + mt * 16 + lg;
                int cc = kb + lt;
                af[mt][0] = As[r * APAD + cc];
                af[mt][1] = As[(r + 8) * APAD + cc];
                af[mt][2] = As[r * APAD + cc + 4];
                af[mt][3] = As[(r + 8) * APAD + cc + 4];
            }
            #pragma unroll
            for (int nt = 0; nt < 4; nt++) {
                int nn = bn0 + nt * 8 + lg;
                int kk = kb + lt;
                bf[nt][0] = Bs[kk * BPAD + nn];
                bf[nt][1] = Bs[(kk + 4) * BPAD + nn];
            }
            #pragma unroll
            for (int mt = 0; mt < 4; mt++)
                #pragma unroll
                for (int nt = 0; nt < 4; nt++)
                    mma_tf32(c[mt][nt], af[mt], bf[nt]);
        }

        __syncthreads();
        if (more) {
            #pragma unroll
            for (int ph = 0; ph < 4; ph++) {
                *(uint4*)&As[a_row[ph] * APAD + a_col[ph]] = pa[ph];
                *(uint4*)&Bs[b_row[ph] * BPAD + b_col[ph]] = pb[ph];
            }
            __syncthreads();
        }
    }

    #pragma unroll
    for (int mt = 0; mt < 4; mt++) {
        int m = m0 + am0 + mt * 16 + lg;
        #pragma unroll
        for (int nt = 0; nt < 4; nt++) {
            int n = n0 + bn0 + nt * 8 + lt * 2;
            float b0 = bias[n], b1 = bias[n + 1];
            int h = n >> 6, d = n & (HD - 1);
            {
                int bb = m >> 10, s = m & (SEQ - 1);
                float2 r2 = make_float2(c[mt][nt][0] + b0, c[mt][nt][1] + b1);
                *(float2*)(out + (((size_t)bb * NH + h) * SEQ + s) * HD + d) = r2;
            }
            {
                int m2 = m + 8;
                int bb = m2 >> 10, s = m2 & (SEQ - 1);
                float2 r2 = make_float2(c[mt][nt][2] + b0, c[mt][nt][3] + b1);
                *(float2*)(out + (((size_t)bb * NH + h) * SEQ + s) * HD + d) = r2;
            }
        }
    }
}

// ---------------------------------------------------------------------------
// Tensor-core flash attention (tf32 mma) with constituency penalty.
// Grid (SEQ/128, NH, B), 256 threads = 8 warps. Each CTA covers 128 q-rows,
// each warp one m16 tile of q-rows. 64-key tiles aligned to constituent
// blocks -> penalty is a per-warp scalar folded into the ex2 argument.
// Q split hi+lo and P split hi+lo for tf32 precision recovery.
// Max-free softmax (scores bounded ~|6|): p = exp(s), divide by sum at end.
// ---------------------------------------------------------------------------
#define KSTRIDE 68   // Ks row stride (words): bank 4*lg+lt all-distinct
#define VSTRIDE 72   // Vs row stride (words): bank 8*lt+lg all-distinct
#define PSTRIDE 68   // P row stride
#define SMEM_K  (64 * KSTRIDE)                 // 4352 words
#define SMEM_V  (64 * VSTRIDE)                 // 4608 words
#define SMEM_PW (16 * PSTRIDE)                 // 1088 words per P buffer
#define ATTN_SMEM_BYTES ((SMEM_K + SMEM_V + 8 * 2 * SMEM_PW) * 4)  // 105472 B

__global__ __launch_bounds__(256, 1) void attn_tc(float* __restrict__ out)
{
    extern __shared__ uint32_t sm[];
    uint32_t* Ks = sm;                       // [64][KSTRIDE]
    uint32_t* Vs = Ks + SMEM_K;              // [64][VSTRIDE]
    const int tid  = threadIdx.x;
    const int lane = tid & 31;
    const int w    = tid >> 5;               // 0..7
    const int lg   = lane >> 2;              // 0..7
    const int lt   = lane & 3;               // 0..3
    uint32_t* Ph = Vs + SMEM_V + w * 2 * SMEM_PW;   // per-warp private
    uint32_t* Pl = Ph + SMEM_PW;

    const int qt = blockIdx.x;               // 0..7 (each = 128 q-rows)
    const int h  = blockIdx.y;
    const int bb = blockIdx.z;
    const size_t bh = (size_t)bb * NH + h;
    const float* Qg = g_q + (bh * SEQ + qt * 128 + w * 16) * HD;
    const float* Kg = g_k + bh * SEQ * HD;
    const float* Vg = g_v + bh * SEQ * HD;

    const int qblk = qt * 2 + (w >> 2);      // constituent block of this warp's q rows

    // ---- load Q fragments once (hi + lo split) ----
    uint32_t qh[8][4], ql[8][4];
    #pragma unroll
    for (int kt = 0; kt < 8; kt++) {
        #pragma unroll
        for (int e = 0; e < 4; e++) {
            int row = lg + (e & 1) * 8;
            int col = kt * 8 + lt + (e >> 1) * 4;
            float qv = Qg[row * HD + col];
            uint32_t hb = f2tf32(qv);
            qh[kt][e] = hb;
            ql[kt][e] = f2tf32(qv - __uint_as_float(hb));
        }
    }

    float o[8][4];
    #pragma unroll
    for (int nt = 0; nt < 8; nt++)
        #pragma unroll
        for (int e = 0; e < 4; e++) o[nt][e] = 0.0f;
    float l0 = 0.0f, l1 = 0.0f;

    const float C1 = 0.18033688f;            // log2(e)/8

    for (int kt64 = 0; kt64 < SEQ / 64; kt64++) {
        __syncthreads();
        // cooperative K/V tile load (convert to tf32 in-flight)
        #pragma unroll
        for (int i = 0; i < 4; i++) {
            int idx = tid + i * 256;         // 0..1023
            int r   = idx >> 4;
            int c4  = (idx & 15) * 4;
            float4 kv = *(const float4*)(Kg + (size_t)kt64 * 64 * HD + r * HD + c4);
            *(uint4*)&Ks[r * KSTRIDE + c4] =
                make_uint4(f2tf32(kv.x), f2tf32(kv.y), f2tf32(kv.z), f2tf32(kv.w));
            float4 vv = *(const float4*)(Vg + (size_t)kt64 * 64 * HD + r * HD + c4);
            *(uint4*)&Vs[r * VSTRIDE + c4] =
                make_uint4(f2tf32(vv.x), f2tf32(vv.y), f2tf32(vv.z), f2tf32(vv.w));
        }
        __syncthreads();

        // ---- S = Q K^T for 16 q-rows x 64 keys ----
        float sc[8][4];
        #pragma unroll
        for (int nt = 0; nt < 8; nt++)
            #pragma unroll
            for (int e = 0; e < 4; e++) sc[nt][e] = 0.0f;

        #pragma unroll
        for (int kt = 0; kt < 8; kt++) {
            #pragma unroll
            for (int nt = 0; nt < 8; nt++) {
                uint32_t bfr[2];
                bfr[0] = Ks[(nt * 8 + lg) * KSTRIDE + kt * 8 + lt];
                bfr[1] = Ks[(nt * 8 + lg) * KSTRIDE + kt * 8 + lt + 4];
                mma_tf32(sc[nt], qh[kt], bfr);
                mma_tf32(sc[nt], ql[kt], bfr);
            }
        }

        // ---- p = exp(s/8 - pen) via ex2; split to hi/lo; per-warp P smem ----
        const float pen2 = (qblk != kt64) ? 0.72134752f : 0.0f;  // 0.5*log2(e)
        #pragma unroll
        for (int nt = 0; nt < 8; nt++) {
            uint32_t ph2[4], pl2[4];
            #pragma unroll
            for (int e = 0; e < 4; e++) {
                float p = ex2(fmaf(sc[nt][e], C1, -pen2));
                if (e < 2) l0 += p; else l1 += p;
                uint32_t hb = f2tf32(p);
                ph2[e] = hb;
                pl2[e] = f2tf32(p - __uint_as_float(hb));
            }
            int c0 = nt * 8 + 2 * lt;
            *(uint2*)&Ph[lg * PSTRIDE + c0]       = make_uint2(ph2[0], ph2[1]);
            *(uint2*)&Ph[(lg + 8) * PSTRIDE + c0] = make_uint2(ph2[2], ph2[3]);
            *(uint2*)&Pl[lg * PSTRIDE + c0]       = make_uint2(pl2[0], pl2[1]);
            *(uint2*)&Pl[(lg + 8) * PSTRIDE + c0] = make_uint2(pl2[2], pl2[3]);
        }
        __syncwarp();

        // ---- O += P V ----
        #pragma unroll
        for (int kt = 0; kt < 8; kt++) {
            uint32_t ah[4], al[4];
            ah[0] = Ph[lg * PSTRIDE + kt * 8 + lt];
            ah[1] = Ph[(lg + 8) * PSTRIDE + kt * 8 + lt];
            ah[2] = Ph[lg * PSTRIDE + kt * 8 + lt + 4];
            ah[3] = Ph[(lg + 8) * PSTRIDE + kt * 8 + lt + 4];
            al[0] = Pl[lg * PSTRIDE + kt * 8 + lt];
            al[1] = Pl[(lg + 8) * PSTRIDE + kt * 8 + lt];
            al[2] = Pl[lg * PSTRIDE + kt * 8 + lt + 4];
            al[3] = Pl[(lg + 8) * PSTRIDE + kt * 8 + lt + 4];
            #pragma unroll
            for (int nt = 0; nt < 8; nt++) {
                uint32_t bfr[2];
                bfr[0] = Vs[(kt * 8 + lt) * VSTRIDE + nt * 8 + lg];
                bfr[1] = Vs[(kt * 8 + lt + 4) * VSTRIDE + nt * 8 + lg];
                mma_tf32(o[nt], ah, bfr);
                mma_tf32(o[nt], al, bfr);
            }
        }
    }

    // ---- normalize and write ----
    l0 += __shfl_xor_sync(0xFFFFFFFFu, l0, 1);
    l0 += __shfl_xor_sync(0xFFFFFFFFu, l0, 2);
    l1 += __shfl_xor_sync(0xFFFFFFFFu, l1, 1);
    l1 += __shfl_xor_sync(0xFFFFFFFFu, l1, 2);
    const float inv0 = 1.0f / l0;
    const float inv1 = 1.0f / l1;

    const int qbase = qt * 128 + w * 16;
    #pragma unroll
    for (int nt = 0; nt < 8; nt++) {
        int d = h * HD + nt * 8 + 2 * lt;
        {
            size_t off = ((size_t)bb * SEQ + qbase + lg) * HID + d;
            *(float2*)(out + off) = make_float2(o[nt][0] * inv0, o[nt][1] * inv0);
        }
        {
            size_t off = ((size_t)bb * SEQ + qbase + lg + 8) * HID + d;
            *(float2*)(out + off) = make_float2(o[nt][2] * inv1, o[nt][3] * inv1);
        }
    }
}

// ---------------------------------------------------------------------------
extern "C" void kernel_launch(void* const* d_in, const int* in_sizes, int n_in,
                              void* d_out, int out_size)
{
    const float* X  = (const float*)d_in[0];
    const float* Wq = (const float*)d_in[1];
    const float* bq = (const float*)d_in[2];
    const float* Wk = (const float*)d_in[3];
    const float* bk = (const float*)d_in[4];
    const float* Wv = (const float*)d_in[5];
    const float* bv = (const float*)d_in[6];

    cudaFuncSetAttribute(attn_tc, cudaFuncAttributeMaxDynamicSharedMemorySize,
                         ATTN_SMEM_BYTES);

    dim3 g1(HID / BN, MTOT / BM, 3);
    qkv_gemm_tf32<<<g1, 256>>>(X, Wq, bq, Wk, bk, Wv, bv);

    dim3 g2(SEQ / 128, NH, BATCH);    // (8,16,8): each CTA = 128 q-rows
    attn_tc<<<g2, 256, ATTN_SMEM_BYTES>>>((float*)d_out);
}

// round 5
// speedup vs baseline: 3.2602x; 2.0493x over previous
#include <cuda_runtime.h>
#include <cstdint>

#define BATCH 8
#define SEQ   1024
#define HID   1024
#define NH    16
#define HD    64
#define MTOT  (BATCH*SEQ)   // 8192

// Scratch (static, no allocs): projected Q/K/V + tf32-pre-rounded inputs.
__device__ float g_q[(size_t)MTOT * HID];
__device__ float g_k[(size_t)MTOT * HID];
__device__ float g_v[(size_t)MTOT * HID];
__device__ float g_xr[(size_t)MTOT * HID];       // rna(X)
__device__ float g_wr[(size_t)3 * HID * HID];    // rna(Wq|Wk|Wv)

__device__ __forceinline__ uint32_t f2tf32(float f) {
    uint32_t u;
    asm("cvt.rna.tf32.f32 %0, %1;" : "=r"(u) : "f"(f));
    return u;
}

__device__ __forceinline__ float ex2(float x) {
    float r;
    asm("ex2.approx.ftz.f32 %0, %1;" : "=f"(r) : "f"(x));
    return r;
}

__device__ __forceinline__ void mma_tf32(float c[4], const uint32_t a[4],
                                         const uint32_t b[2]) {
    asm volatile(
        "mma.sync.aligned.m16n8k8.row.col.f32.tf32.tf32.f32 "
        "{%0,%1,%2,%3}, {%4,%5,%6,%7}, {%8,%9}, {%0,%1,%2,%3};\n"
        : "+f"(c[0]), "+f"(c[1]), "+f"(c[2]), "+f"(c[3])
        : "r"(a[0]), "r"(a[1]), "r"(a[2]), "r"(a[3]), "r"(b[0]), "r"(b[1]));
}

__device__ __forceinline__ void cp16(uint32_t smem_addr, const void* gptr) {
    asm volatile("cp.async.ca.shared.global [%0], [%1], 16;\n"
                 :: "r"(smem_addr), "l"(gptr));
}
__device__ __forceinline__ void cp_commit() {
    asm volatile("cp.async.commit_group;\n");
}
__device__ __forceinline__ void cp_wait0() {
    asm volatile("cp.async.wait_group 0;\n");
}

// ---------------------------------------------------------------------------
// Prologue: round a float array to tf32 (rna) — makes cp.async numerics
// identical to the previous cvt-at-load path.
// ---------------------------------------------------------------------------
__global__ __launch_bounds__(256) void round_tf32(const float* __restrict__ src,
                                                  float* __restrict__ dst, int n4)
{
    int i = blockIdx.x * 256 + threadIdx.x;
    if (i < n4) {
        float4 v = ((const float4*)src)[i];
        float4 r;
        r.x = __uint_as_float(f2tf32(v.x));
        r.y = __uint_as_float(f2tf32(v.y));
        r.z = __uint_as_float(f2tf32(v.z));
        r.w = __uint_as_float(f2tf32(v.w));
        ((float4*)dst)[i] = r;
    }
}

// ---------------------------------------------------------------------------
// TF32 QKV projection, cp.async 2-stage pipeline, one barrier per k-iter.
// A row-major [128][ASTRIDE], B row-major [32][BSTRIDE]. 2 CTAs/SM.
// Epilogue: Q written raw fp32; K,V written tf32-rounded (consumed by
// cp.async in the attention kernel with identical numerics).
// ---------------------------------------------------------------------------
#define BM 128
#define BN 128
#define BK 32
#define ASTRIDE 36
#define BSTRIDE 136
#define G_A_WORDS (BM * ASTRIDE)            // 4608
#define G_B_WORDS (BK * BSTRIDE)            // 4352
#define G_STAGE   (G_A_WORDS + G_B_WORDS)   // 8960 words
#define GEMM_SMEM_BYTES (2 * G_STAGE * 4)   // 71680 B

__global__ __launch_bounds__(256, 2) void qkv_gemm_tf32(
    const float* __restrict__ X,      // pre-rounded
    const float* __restrict__ Wall,   // pre-rounded, 3 stacked
    const float* __restrict__ bq, const float* __restrict__ bk,
    const float* __restrict__ bv)
{
    extern __shared__ uint32_t smg[];
    const int z = blockIdx.z;
    const float* W = Wall + (size_t)z * HID * HID;
    const float* bias = (z == 0) ? bq : (z == 1) ? bk : bv;
    float* out = (z == 0) ? g_q : (z == 1) ? g_k : g_v;

    const int tid  = threadIdx.x;
    const int lane = tid & 31;
    const int w    = tid >> 5;
    const int wm   = w >> 2;
    const int wn   = w & 3;
    const int m0   = blockIdx.y * BM;
    const int n0   = blockIdx.x * BN;
    const int lg   = lane >> 2;
    const int lt   = lane & 3;
    const int am0  = wm * 64;
    const int bn0  = wn * 32;

    uint32_t smem_base;
    { void* p = smg; smem_base = (uint32_t)__cvta_generic_to_shared(p); }

    // per-thread copy slices
    int a_r[4], a_c[4], b_r[4], b_c[4];
    #pragma unroll
    for (int p = 0; p < 4; p++) {
        int ia = tid + p * 256;          // 0..1023
        a_r[p] = ia >> 3;                // 0..127
        a_c[p] = (ia & 7) * 4;           // 0..28
        b_r[p] = ia >> 5;                // 0..31
        b_c[p] = (ia & 31) * 4;          // 0..124
    }

    auto issue = [&](int stage, int k0) {
        uint32_t ab = smem_base + stage * G_STAGE * 4;
        uint32_t bb2 = ab + G_A_WORDS * 4;
        #pragma unroll
        for (int p = 0; p < 4; p++)
            cp16(ab + (a_r[p] * ASTRIDE + a_c[p]) * 4,
                 X + (size_t)(m0 + a_r[p]) * HID + k0 + a_c[p]);
        #pragma unroll
        for (int p = 0; p < 4; p++)
            cp16(bb2 + (b_r[p] * BSTRIDE + b_c[p]) * 4,
                 W + (size_t)(k0 + b_r[p]) * HID + n0 + b_c[p]);
        cp_commit();
    };

    float c[4][4][4];
    #pragma unroll
    for (int mt = 0; mt < 4; mt++)
        #pragma unroll
        for (int nt = 0; nt < 4; nt++)
            #pragma unroll
            for (int i = 0; i < 4; i++) c[mt][nt][i] = 0.0f;

    issue(0, 0);

    for (int ki = 0; ki < HID / BK; ki++) {
        cp_wait0();
        __syncthreads();
        if (ki + 1 < HID / BK) issue((ki + 1) & 1, (ki + 1) * BK);

        const uint32_t* Asp = smg + (ki & 1) * G_STAGE;
        const uint32_t* Bsp = Asp + G_A_WORDS;

        #pragma unroll
        for (int kt = 0; kt < 4; kt++) {
            const int kb = kt * 8;
            uint32_t af[4][4], bf[4][2];
            #pragma unroll
            for (int mt = 0; mt < 4; mt++) {
                int r  = am0 + mt * 16 + lg;
                int cc = kb + lt;
                af[mt][0] = Asp[r * ASTRIDE + cc];
                af[mt][1] = Asp[(r + 8) * ASTRIDE + cc];
                af[mt][2] = Asp[r * ASTRIDE + cc + 4];
                af[mt][3] = Asp[(r + 8) * ASTRIDE + cc + 4];
            }
            #pragma unroll
            for (int nt = 0; nt < 4; nt++) {
                int nn = bn0 + nt * 8 + lg;
                int kk = kb + lt;
                bf[nt][0] = Bsp[kk * BSTRIDE + nn];
                bf[nt][1] = Bsp[(kk + 4) * BSTRIDE + nn];
            }
            #pragma unroll
            for (int mt = 0; mt < 4; mt++)
                #pragma unroll
                for (int nt = 0; nt < 4; nt++)
                    mma_tf32(c[mt][nt], af[mt], bf[nt]);
        }
        __syncthreads();
    }

    // epilogue: bias add; K/V rounded to tf32, Q raw; scatter [B,nh,S,hd]
    const bool rnd = (z != 0);
    #pragma unroll
    for (int mt = 0; mt < 4; mt++) {
        int m = m0 + am0 + mt * 16 + lg;
        #pragma unroll
        for (int nt = 0; nt < 4; nt++) {
            int n = n0 + bn0 + nt * 8 + lt * 2;
            float b0 = bias[n], b1 = bias[n + 1];
            int h = n >> 6, d = n & (HD - 1);
            #pragma unroll
            for (int half = 0; half < 2; half++) {
                int mm = m + half * 8;
                int bb = mm >> 10, s = mm & (SEQ - 1);
                float v0 = c[mt][nt][half * 2]     + b0;
                float v1 = c[mt][nt][half * 2 + 1] + b1;
                if (rnd) {
                    v0 = __uint_as_float(f2tf32(v0));
                    v1 = __uint_as_float(f2tf32(v1));
                }
                *(float2*)(out + (((size_t)bb * NH + h) * SEQ + s) * HD + d) =
                    make_float2(v0, v1);
            }
        }
    }
}

// ---------------------------------------------------------------------------
// Tensor-core flash attention, cp.async 2-stage K/V pipeline.
// Grid (SEQ/128, NH, B), 256 threads = 8 warps, warp = 16 q-rows.
// K/V arrive pre-rounded to tf32 from the GEMM epilogue.
// ---------------------------------------------------------------------------
#define KSTRIDE 68
#define VSTRIDE 72
#define PSTRIDE 68
#define SMEM_K  (64 * KSTRIDE)               // 4352 words
#define SMEM_V  (64 * VSTRIDE)               // 4608 words
#define A_STAGE (SMEM_K + SMEM_V)            // 8960 words
#define SMEM_PW (16 * PSTRIDE)               // 1088 words
#define ATTN_SMEM_BYTES ((2 * A_STAGE + 8 * 2 * SMEM_PW) * 4)   // 141312 B

__global__ __launch_bounds__(256, 1) void attn_tc(float* __restrict__ out)
{
    extern __shared__ uint32_t sm[];
    const int tid  = threadIdx.x;
    const int lane = tid & 31;
    const int w    = tid >> 5;
    const int lg   = lane >> 2;
    const int lt   = lane & 3;
    uint32_t* Ph = sm + 2 * A_STAGE + w * 2 * SMEM_PW;
    uint32_t* Pl = Ph + SMEM_PW;

    const int qt = blockIdx.x;
    const int h  = blockIdx.y;
    const int bb = blockIdx.z;
    const size_t bh = (size_t)bb * NH + h;
    const float* Qg = g_q + (bh * SEQ + qt * 128 + w * 16) * HD;
    const float* Kg = g_k + bh * SEQ * HD;
    const float* Vg = g_v + bh * SEQ * HD;

    const int qblk = qt * 2 + (w >> 2);

    uint32_t smem_base;
    { void* p = sm; smem_base = (uint32_t)__cvta_generic_to_shared(p); }

    auto issueKV = [&](int stage, int tile) {
        uint32_t kb2 = smem_base + stage * A_STAGE * 4;
        uint32_t vb2 = kb2 + SMEM_K * 4;
        #pragma unroll
        for (int i = 0; i < 4; i++) {
            int idx = tid + i * 256;         // 0..1023
            int r   = idx >> 4;
            int c4  = (idx & 15) * 4;
            cp16(kb2 + (r * KSTRIDE + c4) * 4,
                 Kg + (size_t)tile * 64 * HD + r * HD + c4);
            cp16(vb2 + (r * VSTRIDE + c4) * 4,
                 Vg + (size_t)tile * 64 * HD + r * HD + c4);
        }
        cp_commit();
    };

    // ---- Q fragments (hi + lo split), loaded once ----
    uint32_t qh[8][4], ql[8][4];
    #pragma unroll
    for (int kt = 0; kt < 8; kt++) {
        #pragma unroll
        for (int e = 0; e < 4; e++) {
            int row = lg + (e & 1) * 8;
            int col = kt * 8 + lt + (e >> 1) * 4;
            float qv = Qg[row * HD + col];
            uint32_t hb = f2tf32(qv);
            qh[kt][e] = hb;
            ql[kt][e] = f2tf32(qv - __uint_as_float(hb));
        }
    }

    float o[8][4];
    #pragma unroll
    for (int nt = 0; nt < 8; nt++)
        #pragma unroll
        for (int e = 0; e < 4; e++) o[nt][e] = 0.0f;
    float l0 = 0.0f, l1 = 0.0f;

    const float C1 = 0.18033688f;            // log2(e)/8

    issueKV(0, 0);

    for (int kt64 = 0; kt64 < SEQ / 64; kt64++) {
        cp_wait0();
        __syncthreads();
        if (kt64 + 1 < SEQ / 64) issueKV((kt64 + 1) & 1, kt64 + 1);

        const uint32_t* Ks = sm + (kt64 & 1) * A_STAGE;
        const uint32_t* Vs = Ks + SMEM_K;

        // ---- S = Q K^T ----
        float sc[8][4];
        #pragma unroll
        for (int nt = 0; nt < 8; nt++)
            #pragma unroll
            for (int e = 0; e < 4; e++) sc[nt][e] = 0.0f;

        #pragma unroll
        for (int kt = 0; kt < 8; kt++) {
            #pragma unroll
            for (int nt = 0; nt < 8; nt++) {
                uint32_t bfr[2];
                bfr[0] = Ks[(nt * 8 + lg) * KSTRIDE + kt * 8 + lt];
                bfr[1] = Ks[(nt * 8 + lg) * KSTRIDE + kt * 8 + lt + 4];
                mma_tf32(sc[nt], qh[kt], bfr);
                mma_tf32(sc[nt], ql[kt], bfr);
            }
        }

        // ---- p = exp2(s*log2e/8 - pen2); split hi/lo into per-warp smem ----
        const float pen2 = (qblk != kt64) ? 0.72134752f : 0.0f;
        #pragma unroll
        for (int nt = 0; nt < 8; nt++) {
            uint32_t ph2[4], pl2[4];
            #pragma unroll
            for (int e = 0; e < 4; e++) {
                float p = ex2(fmaf(sc[nt][e], C1, -pen2));
                if (e < 2) l0 += p; else l1 += p;
                uint32_t hb = f2tf32(p);
                ph2[e] = hb;
                pl2[e] = f2tf32(p - __uint_as_float(hb));
            }
            int c0 = nt * 8 + 2 * lt;
            *(uint2*)&Ph[lg * PSTRIDE + c0]       = make_uint2(ph2[0], ph2[1]);
            *(uint2*)&Ph[(lg + 8) * PSTRIDE + c0] = make_uint2(ph2[2], ph2[3]);
            *(uint2*)&Pl[lg * PSTRIDE + c0]       = make_uint2(pl2[0], pl2[1]);
            *(uint2*)&Pl[(lg + 8) * PSTRIDE + c0] = make_uint2(pl2[2], pl2[3]);
        }
        __syncwarp();

        // ---- O += P V ----
        #pragma unroll
        for (int kt = 0; kt < 8; kt++) {
            uint32_t ah[4], al[4];
            ah[0] = Ph[lg * PSTRIDE + kt * 8 + lt];
            ah[1] = Ph[(lg + 8) * PSTRIDE + kt * 8 + lt];
            ah[2] = Ph[lg * PSTRIDE + kt * 8 + lt + 4];
            ah[3] = Ph[(lg + 8) * PSTRIDE + kt * 8 + lt + 4];
            al[0] = Pl[lg * PSTRIDE + kt * 8 + lt];
            al[1] = Pl[(lg + 8) * PSTRIDE + kt * 8 + lt];
            al[2] = Pl[lg * PSTRIDE + kt * 8 + lt + 4];
            al[3] = Pl[(lg + 8) * PSTRIDE + kt * 8 + lt + 4];
            #pragma unroll
            for (int nt = 0; nt < 8; nt++) {
                uint32_t bfr[2];
                bfr[0] = Vs[(kt * 8 + lt) * VSTRIDE + nt * 8 + lg];
                bfr[1] = Vs[(kt * 8 + lt + 4) * VSTRIDE + nt * 8 + lg];
                mma_tf32(o[nt], ah, bfr);
                mma_tf32(o[nt], al, bfr);
            }
        }
        __syncthreads();   // protect stage buffer (next issue overwrites)
    }

    // ---- normalize and write ----
    l0 += __shfl_xor_sync(0xFFFFFFFFu, l0, 1);
    l0 += __shfl_xor_sync(0xFFFFFFFFu, l0, 2);
    l1 += __shfl_xor_sync(0xFFFFFFFFu, l1, 1);
    l1 += __shfl_xor_sync(0xFFFFFFFFu, l1, 2);
    const float inv0 = 1.0f / l0;
    const float inv1 = 1.0f / l1;

    const int qbase = qt * 128 + w * 16;
    #pragma unroll
    for (int nt = 0; nt < 8; nt++) {
        int d = h * HD + nt * 8 + 2 * lt;
        {
            size_t off = ((size_t)bb * SEQ + qbase + lg) * HID + d;
            *(float2*)(out + off) = make_float2(o[nt][0] * inv0, o[nt][1] * inv0);
        }
        {
            size_t off = ((size_t)bb * SEQ + qbase + lg + 8) * HID + d;
            *(float2*)(out + off) = make_float2(o[nt][2] * inv1, o[nt][3] * inv1);
        }
    }
}

// ---------------------------------------------------------------------------
extern "C" void kernel_launch(void* const* d_in, const int* in_sizes, int n_in,
                              void* d_out, int out_size)
{
    const float* X  = (const float*)d_in[0];
    const float* Wq = (const float*)d_in[1];
    const float* bq = (const float*)d_in[2];
    const float* Wk = (const float*)d_in[3];
    const float* bk = (const float*)d_in[4];
    const float* Wv = (const float*)d_in[5];
    const float* bv = (const float*)d_in[6];

    cudaFuncSetAttribute(qkv_gemm_tf32, cudaFuncAttributeMaxDynamicSharedMemorySize,
                         GEMM_SMEM_BYTES);
    cudaFuncSetAttribute(attn_tc, cudaFuncAttributeMaxDynamicSharedMemorySize,
                         ATTN_SMEM_BYTES);

    float *xr, *wr;
    cudaGetSymbolAddress((void**)&xr, g_xr);
    cudaGetSymbolAddress((void**)&wr, g_wr);

    // prologue: pre-round X and Ws to tf32 (numerics identical to cvt-at-load)
    {
        int n4 = MTOT * HID / 4;                     // 2M float4
        round_tf32<<<(n4 + 255) / 256, 256>>>(X, xr, n4);
        int w4 = HID * HID / 4;                      // 256K float4
        round_tf32<<<(w4 + 255) / 256, 256>>>(Wq, wr, w4);
        round_tf32<<<(w4 + 255) / 256, 256>>>(Wk, wr + (size_t)HID * HID, w4);
        round_tf32<<<(w4 + 255) / 256, 256>>>(Wv, wr + (size_t)2 * HID * HID, w4);
    }

    dim3 g1(HID / BN, MTOT / BM, 3);
    qkv_gemm_tf32<<<g1, 256, GEMM_SMEM_BYTES>>>(xr, wr, bq, bk, bv);

    dim3 g2(SEQ / 128, NH, BATCH);
    attn_tc<<<g2, 256, ATTN_SMEM_BYTES>>>((float*)d_out);
}

// round 6
// speedup vs baseline: 3.6376x; 1.1158x over previous
#include <cuda_runtime.h>
#include <cstdint>

#define BATCH 8
#define SEQ   1024
#define HID   1024
#define NH    16
#define HD    64
#define MTOT  (BATCH*SEQ)   // 8192

// Scratch (static, no allocs): projected Q/K/V + tf32-pre-rounded inputs.
__device__ float g_q[(size_t)MTOT * HID];
__device__ float g_k[(size_t)MTOT * HID];
__device__ float g_v[(size_t)MTOT * HID];
__device__ float g_xr[(size_t)MTOT * HID];       // rna(X)
__device__ float g_wr[(size_t)3 * HID * HID];    // rna(Wq|Wk|Wv)

__device__ __forceinline__ uint32_t f2tf32(float f) {
    uint32_t u;
    asm("cvt.rna.tf32.f32 %0, %1;" : "=r"(u) : "f"(f));
    return u;
}

__device__ __forceinline__ float ex2(float x) {
    float r;
    asm("ex2.approx.ftz.f32 %0, %1;" : "=f"(r) : "f"(x));
    return r;
}

__device__ __forceinline__ void mma_tf32(float c[4], const uint32_t a[4],
                                         const uint32_t b[2]) {
    asm volatile(
        "mma.sync.aligned.m16n8k8.row.col.f32.tf32.tf32.f32 "
        "{%0,%1,%2,%3}, {%4,%5,%6,%7}, {%8,%9}, {%0,%1,%2,%3};\n"
        : "+f"(c[0]), "+f"(c[1]), "+f"(c[2]), "+f"(c[3])
        : "r"(a[0]), "r"(a[1]), "r"(a[2]), "r"(a[3]), "r"(b[0]), "r"(b[1]));
}

__device__ __forceinline__ void cp16(uint32_t smem_addr, const void* gptr) {
    asm volatile("cp.async.ca.shared.global [%0], [%1], 16;\n"
                 :: "r"(smem_addr), "l"(gptr));
}
__device__ __forceinline__ void cp_commit() {
    asm volatile("cp.async.commit_group;\n");
}
__device__ __forceinline__ void cp_wait0() {
    asm volatile("cp.async.wait_group 0;\n");
}

// ---------------------------------------------------------------------------
// Prologue: round float array to tf32 (rna). Grid-stride, 4 float4/iter (MLP=4).
// ---------------------------------------------------------------------------
__global__ __launch_bounds__(256) void round_tf32(const float* __restrict__ src,
                                                  float* __restrict__ dst, int n4)
{
    const int stride = gridDim.x * 256;
    for (int i0 = blockIdx.x * 256 + threadIdx.x; i0 < n4; i0 += 4 * stride) {
        float4 v[4];
        int idx[4];
        #pragma unroll
        for (int u = 0; u < 4; u++) {
            idx[u] = i0 + u * stride;
            if (idx[u] < n4) v[u] = ((const float4*)src)[idx[u]];
        }
        #pragma unroll
        for (int u = 0; u < 4; u++) {
            if (idx[u] < n4) {
                float4 r;
                r.x = __uint_as_float(f2tf32(v[u].x));
                r.y = __uint_as_float(f2tf32(v[u].y));
                r.z = __uint_as_float(f2tf32(v[u].z));
                r.w = __uint_as_float(f2tf32(v[u].w));
                ((float4*)dst)[idx[u]] = r;
            }
        }
    }
}

// ---------------------------------------------------------------------------
// TF32 QKV projection, cp.async 2-stage pipeline (unchanged from R5).
// Q written raw fp32; K,V tf32-rounded for the attention cp.async path.
// ---------------------------------------------------------------------------
#define BM 128
#define BN 128
#define BK 32
#define ASTRIDE 36
#define BSTRIDE 136
#define G_A_WORDS (BM * ASTRIDE)            // 4608
#define G_B_WORDS (BK * BSTRIDE)            // 4352
#define G_STAGE   (G_A_WORDS + G_B_WORDS)   // 8960 words
#define GEMM_SMEM_BYTES (2 * G_STAGE * 4)   // 71680 B

__global__ __launch_bounds__(256, 2) void qkv_gemm_tf32(
    const float* __restrict__ X,
    const float* __restrict__ Wall,
    const float* __restrict__ bq, const float* __restrict__ bk,
    const float* __restrict__ bv)
{
    extern __shared__ uint32_t smg[];
    const int z = blockIdx.z;
    const float* W = Wall + (size_t)z * HID * HID;
    const float* bias = (z == 0) ? bq : (z == 1) ? bk : bv;
    float* out = (z == 0) ? g_q : (z == 1) ? g_k : g_v;

    const int tid  = threadIdx.x;
    const int lane = tid & 31;
    const int w    = tid >> 5;
    const int wm   = w >> 2;
    const int wn   = w & 3;
    const int m0   = blockIdx.y * BM;
    const int n0   = blockIdx.x * BN;
    const int lg   = lane >> 2;
    const int lt   = lane & 3;
    const int am0  = wm * 64;
    const int bn0  = wn * 32;

    uint32_t smem_base;
    { void* p = smg; smem_base = (uint32_t)__cvta_generic_to_shared(p); }

    int a_r[4], a_c[4], b_r[4], b_c[4];
    #pragma unroll
    for (int p = 0; p < 4; p++) {
        int ia = tid + p * 256;
        a_r[p] = ia >> 3;
        a_c[p] = (ia & 7) * 4;
        b_r[p] = ia >> 5;
        b_c[p] = (ia & 31) * 4;
    }

    auto issue = [&](int stage, int k0) {
        uint32_t ab = smem_base + stage * G_STAGE * 4;
        uint32_t bb2 = ab + G_A_WORDS * 4;
        #pragma unroll
        for (int p = 0; p < 4; p++)
            cp16(ab + (a_r[p] * ASTRIDE + a_c[p]) * 4,
                 X + (size_t)(m0 + a_r[p]) * HID + k0 + a_c[p]);
        #pragma unroll
        for (int p = 0; p < 4; p++)
            cp16(bb2 + (b_r[p] * BSTRIDE + b_c[p]) * 4,
                 W + (size_t)(k0 + b_r[p]) * HID + n0 + b_c[p]);
        cp_commit();
    };

    float c[4][4][4];
    #pragma unroll
    for (int mt = 0; mt < 4; mt++)
        #pragma unroll
        for (int nt = 0; nt < 4; nt++)
            #pragma unroll
            for (int i = 0; i < 4; i++) c[mt][nt][i] = 0.0f;

    issue(0, 0);

    for (int ki = 0; ki < HID / BK; ki++) {
        cp_wait0();
        __syncthreads();
        if (ki + 1 < HID / BK) issue((ki + 1) & 1, (ki + 1) * BK);

        const uint32_t* Asp = smg + (ki & 1) * G_STAGE;
        const uint32_t* Bsp = Asp + G_A_WORDS;

        #pragma unroll
        for (int kt = 0; kt < 4; kt++) {
            const int kb = kt * 8;
            uint32_t af[4][4], bf[4][2];
            #pragma unroll
            for (int mt = 0; mt < 4; mt++) {
                int r  = am0 + mt * 16 + lg;
                int cc = kb + lt;
                af[mt][0] = Asp[r * ASTRIDE + cc];
                af[mt][1] = Asp[(r + 8) * ASTRIDE + cc];
                af[mt][2] = Asp[r * ASTRIDE + cc + 4];
                af[mt][3] = Asp[(r + 8) * ASTRIDE + cc + 4];
            }
            #pragma unroll
            for (int nt = 0; nt < 4; nt++) {
                int nn = bn0 + nt * 8 + lg;
                int kk = kb + lt;
                bf[nt][0] = Bsp[kk * BSTRIDE + nn];
                bf[nt][1] = Bsp[(kk + 4) * BSTRIDE + nn];
            }
            #pragma unroll
            for (int mt = 0; mt < 4; mt++)
                #pragma unroll
                for (int nt = 0; nt < 4; nt++)
                    mma_tf32(c[mt][nt], af[mt], bf[nt]);
        }
        __syncthreads();
    }

    const bool rnd = (z != 0);
    #pragma unroll
    for (int mt = 0; mt < 4; mt++) {
        int m = m0 + am0 + mt * 16 + lg;
        #pragma unroll
        for (int nt = 0; nt < 4; nt++) {
            int n = n0 + bn0 + nt * 8 + lt * 2;
            float b0 = bias[n], b1 = bias[n + 1];
            int h = n >> 6, d = n & (HD - 1);
            #pragma unroll
            for (int half = 0; half < 2; half++) {
                int mm = m + half * 8;
                int bb = mm >> 10, s = mm & (SEQ - 1);
                float v0 = c[mt][nt][half * 2]     + b0;
                float v1 = c[mt][nt][half * 2 + 1] + b1;
                if (rnd) {
                    v0 = __uint_as_float(f2tf32(v0));
                    v1 = __uint_as_float(f2tf32(v1));
                }
                *(float2*)(out + (((size_t)bb * NH + h) * SEQ + s) * HD + d) =
                    make_float2(v0, v1);
            }
        }
    }
}

// ---------------------------------------------------------------------------
// Tensor-core flash attention, cp.async 2-stage K/V pipeline.
// Q split hi+lo; P single tf32 (lo-split dropped: output rel err += ~4.9e-4 RSS).
// ---------------------------------------------------------------------------
#define KSTRIDE 68
#define VSTRIDE 72
#define PSTRIDE 68
#define SMEM_K  (64 * KSTRIDE)               // 4352 words
#define SMEM_V  (64 * VSTRIDE)               // 4608 words
#define A_STAGE (SMEM_K + SMEM_V)            // 8960 words
#define SMEM_PW (16 * PSTRIDE)               // 1088 words
#define ATTN_SMEM_BYTES ((2 * A_STAGE + 8 * SMEM_PW) * 4)   // 106496 B

__global__ __launch_bounds__(256, 1) void attn_tc(float* __restrict__ out)
{
    extern __shared__ uint32_t sm[];
    const int tid  = threadIdx.x;
    const int lane = tid & 31;
    const int w    = tid >> 5;
    const int lg   = lane >> 2;
    const int lt   = lane & 3;
    uint32_t* Ph = sm + 2 * A_STAGE + w * SMEM_PW;   // per-warp private P

    const int qt = blockIdx.x;
    const int h  = blockIdx.y;
    const int bb = blockIdx.z;
    const size_t bh = (size_t)bb * NH + h;
    const float* Qg = g_q + (bh * SEQ + qt * 128 + w * 16) * HD;
    const float* Kg = g_k + bh * SEQ * HD;
    const float* Vg = g_v + bh * SEQ * HD;

    const int qblk = qt * 2 + (w >> 2);

    uint32_t smem_base;
    { void* p = sm; smem_base = (uint32_t)__cvta_generic_to_shared(p); }

    auto issueKV = [&](int stage, int tile) {
        uint32_t kb2 = smem_base + stage * A_STAGE * 4;
        uint32_t vb2 = kb2 + SMEM_K * 4;
        #pragma unroll
        for (int i = 0; i < 4; i++) {
            int idx = tid + i * 256;
            int r   = idx >> 4;
            int c4  = (idx & 15) * 4;
            cp16(kb2 + (r * KSTRIDE + c4) * 4,
                 Kg + (size_t)tile * 64 * HD + r * HD + c4);
            cp16(vb2 + (r * VSTRIDE + c4) * 4,
                 Vg + (size_t)tile * 64 * HD + r * HD + c4);
        }
        cp_commit();
    };

    // ---- Q fragments (hi + lo split), loaded once ----
    uint32_t qh[8][4], ql[8][4];
    #pragma unroll
    for (int kt = 0; kt < 8; kt++) {
        #pragma unroll
        for (int e = 0; e < 4; e++) {
            int row = lg + (e & 1) * 8;
            int col = kt * 8 + lt + (e >> 1) * 4;
            float qv = Qg[row * HD + col];
            uint32_t hb = f2tf32(qv);
            qh[kt][e] = hb;
            ql[kt][e] = f2tf32(qv - __uint_as_float(hb));
        }
    }

    float o[8][4];
    #pragma unroll
    for (int nt = 0; nt < 8; nt++)
        #pragma unroll
        for (int e = 0; e < 4; e++) o[nt][e] = 0.0f;
    float l0 = 0.0f, l1 = 0.0f;

    const float C1 = 0.18033688f;            // log2(e)/8

    issueKV(0, 0);

    for (int kt64 = 0; kt64 < SEQ / 64; kt64++) {
        cp_wait0();
        __syncthreads();
        if (kt64 + 1 < SEQ / 64) issueKV((kt64 + 1) & 1, kt64 + 1);

        const uint32_t* Ks = sm + (kt64 & 1) * A_STAGE;
        const uint32_t* Vs = Ks + SMEM_K;

        // ---- S = Q K^T ----
        float sc[8][4];
        #pragma unroll
        for (int nt = 0; nt < 8; nt++)
            #pragma unroll
            for (int e = 0; e < 4; e++) sc[nt][e] = 0.0f;

        #pragma unroll
        for (int kt = 0; kt < 8; kt++) {
            #pragma unroll
            for (int nt = 0; nt < 8; nt++) {
                uint32_t bfr[2];
                bfr[0] = Ks[(nt * 8 + lg) * KSTRIDE + kt * 8 + lt];
                bfr[1] = Ks[(nt * 8 + lg) * KSTRIDE + kt * 8 + lt + 4];
                mma_tf32(sc[nt], qh[kt], bfr);
                mma_tf32(sc[nt], ql[kt], bfr);
            }
        }

        // ---- p = exp2(s*log2e/8 - pen2) -> tf32 -> per-warp P smem ----
        const float pen2 = (qblk != kt64) ? 0.72134752f : 0.0f;
        #pragma unroll
        for (int nt = 0; nt < 8; nt++) {
            uint32_t ph2[4];
            #pragma unroll
            for (int e = 0; e < 4; e++) {
                float p = ex2(fmaf(sc[nt][e], C1, -pen2));
                if (e < 2) l0 += p; else l1 += p;
                ph2[e] = f2tf32(p);
            }
            int c0 = nt * 8 + 2 * lt;
            *(uint2*)&Ph[lg * PSTRIDE + c0]       = make_uint2(ph2[0], ph2[1]);
            *(uint2*)&Ph[(lg + 8) * PSTRIDE + c0] = make_uint2(ph2[2], ph2[3]);
        }
        __syncwarp();

        // ---- O += P V ----
        #pragma unroll
        for (int kt = 0; kt < 8; kt++) {
            uint32_t ah[4];
            ah[0] = Ph[lg * PSTRIDE + kt * 8 + lt];
            ah[1] = Ph[(lg + 8) * PSTRIDE + kt * 8 + lt];
            ah[2] = Ph[lg * PSTRIDE + kt * 8 + lt + 4];
            ah[3] = Ph[(lg + 8) * PSTRIDE + kt * 8 + lt + 4];
            #pragma unroll
            for (int nt = 0; nt < 8; nt++) {
                uint32_t bfr[2];
                bfr[0] = Vs[(kt * 8 + lt) * VSTRIDE + nt * 8 + lg];
                bfr[1] = Vs[(kt * 8 + lt + 4) * VSTRIDE + nt * 8 + lg];
                mma_tf32(o[nt], ah, bfr);
            }
        }
        __syncthreads();   // protect stage buffer before next issue overwrites
    }

    // ---- normalize and write ----
    l0 += __shfl_xor_sync(0xFFFFFFFFu, l0, 1);
    l0 += __shfl_xor_sync(0xFFFFFFFFu, l0, 2);
    l1 += __shfl_xor_sync(0xFFFFFFFFu, l1, 1);
    l1 += __shfl_xor_sync(0xFFFFFFFFu, l1, 2);
    const float inv0 = 1.0f / l0;
    const float inv1 = 1.0f / l1;

    const int qbase = qt * 128 + w * 16;
    #pragma unroll
    for (int nt = 0; nt < 8; nt++) {
        int d = h * HD + nt * 8 + 2 * lt;
        {
            size_t off = ((size_t)bb * SEQ + qbase + lg) * HID + d;
            *(float2*)(out + off) = make_float2(o[nt][0] * inv0, o[nt][1] * inv0);
        }
        {
            size_t off = ((size_t)bb * SEQ + qbase + lg + 8) * HID + d;
            *(float2*)(out + off) = make_float2(o[nt][2] * inv1, o[nt][3] * inv1);
        }
    }
}

// ---------------------------------------------------------------------------
extern "C" void kernel_launch(void* const* d_in, const int* in_sizes, int n_in,
                              void* d_out, int out_size)
{
    const float* X  = (const float*)d_in[0];
    const float* Wq = (const float*)d_in[1];
    const float* bq = (const float*)d_in[2];
    const float* Wk = (const float*)d_in[3];
    const float* bk = (const float*)d_in[4];
    const float* Wv = (const float*)d_in[5];
    const float* bv = (const float*)d_in[6];

    cudaFuncSetAttribute(qkv_gemm_tf32, cudaFuncAttributeMaxDynamicSharedMemorySize,
                         GEMM_SMEM_BYTES);
    cudaFuncSetAttribute(attn_tc, cudaFuncAttributeMaxDynamicSharedMemorySize,
                         ATTN_SMEM_BYTES);

    float *xr, *wr;
    cudaGetSymbolAddress((void**)&xr, g_xr);
    cudaGetSymbolAddress((void**)&wr, g_wr);

    // prologue: pre-round X and Ws to tf32 (numerics identical to cvt-at-load)
    {
        int n4 = MTOT * HID / 4;
        round_tf32<<<1024, 256>>>(X, xr, n4);
        int w4 = HID * HID / 4;
        round_tf32<<<256, 256>>>(Wq, wr, w4);
        round_tf32<<<256, 256>>>(Wk, wr + (size_t)HID * HID, w4);
        round_tf32<<<256, 256>>>(Wv, wr + (size_t)2 * HID * HID, w4);
    }

    dim3 g1(HID / BN, MTOT / BM, 3);
    qkv_gemm_tf32<<<g1, 256, GEMM_SMEM_BYTES>>>(xr, wr, bq, bk, bv);

    dim3 g2(SEQ / 128, NH, BATCH);
    attn_tc<<<g2, 256, ATTN_SMEM_BYTES>>>((float*)d_out);
}

// round 7
// speedup vs baseline: 3.8392x; 1.0554x over previous
#include <cuda_runtime.h>
#include <cstdint>

#define BATCH 8
#define SEQ   1024
#define HID   1024
#define NH    16
#define HD    64
#define MTOT  (BATCH*SEQ)   // 8192

// Scratch (static, no allocs): projected Q/K/V + tf32-pre-rounded inputs.
__device__ float g_q[(size_t)MTOT * HID];
__device__ float g_k[(size_t)MTOT * HID];
__device__ float g_v[(size_t)MTOT * HID];
__device__ float g_xr[(size_t)MTOT * HID];       // rna(X)
__device__ float g_wr[(size_t)3 * HID * HID];    // rna(Wq|Wk|Wv)

__device__ __forceinline__ uint32_t f2tf32(float f) {
    uint32_t u;
    asm("cvt.rna.tf32.f32 %0, %1;" : "=r"(u) : "f"(f));
    return u;
}

__device__ __forceinline__ float ex2(float x) {
    float r;
    asm("ex2.approx.ftz.f32 %0, %1;" : "=f"(r) : "f"(x));
    return r;
}

__device__ __forceinline__ void mma_tf32(float c[4], const uint32_t a[4],
                                         const uint32_t b[2]) {
    asm volatile(
        "mma.sync.aligned.m16n8k8.row.col.f32.tf32.tf32.f32 "
        "{%0,%1,%2,%3}, {%4,%5,%6,%7}, {%8,%9}, {%0,%1,%2,%3};\n"
        : "+f"(c[0]), "+f"(c[1]), "+f"(c[2]), "+f"(c[3])
        : "r"(a[0]), "r"(a[1]), "r"(a[2]), "r"(a[3]), "r"(b[0]), "r"(b[1]));
}

__device__ __forceinline__ void cp16(uint32_t smem_addr, const void* gptr) {
    asm volatile("cp.async.ca.shared.global [%0], [%1], 16;\n"
                 :: "r"(smem_addr), "l"(gptr));
}
__device__ __forceinline__ void cp_commit() {
    asm volatile("cp.async.commit_group;\n");
}
__device__ __forceinline__ void cp_wait1() {
    asm volatile("cp.async.wait_group 1;\n");
}

// ---------------------------------------------------------------------------
// Prologue (single launch): round X and the 3 W matrices to tf32 (rna).
// gridDim.y selects the segment; grid-stride with 4-deep MLP.
// ---------------------------------------------------------------------------
__global__ __launch_bounds__(256) void round_all(
    const float* __restrict__ X,
    const float* __restrict__ Wq, const float* __restrict__ Wk,
    const float* __restrict__ Wv,
    float* __restrict__ xr, float* __restrict__ wr)
{
    const int seg = blockIdx.y;
    const float* src;
    float* dst;
    int n4;
    if (seg == 0)      { src = X;  dst = xr; n4 = MTOT * HID / 4; }
    else if (seg == 1) { src = Wq; dst = wr;                        n4 = HID * HID / 4; }
    else if (seg == 2) { src = Wk; dst = wr + (size_t)HID * HID;    n4 = HID * HID / 4; }
    else               { src = Wv; dst = wr + (size_t)2 * HID * HID; n4 = HID * HID / 4; }

    const int stride = gridDim.x * 256;
    for (int i0 = blockIdx.x * 256 + threadIdx.x; i0 < n4; i0 += 4 * stride) {
        float4 v[4];
        int idx[4];
        #pragma unroll
        for (int u = 0; u < 4; u++) {
            idx[u] = i0 + u * stride;
            if (idx[u] < n4) v[u] = ((const float4*)src)[idx[u]];
        }
        #pragma unroll
        for (int u = 0; u < 4; u++) {
            if (idx[u] < n4) {
                float4 r;
                r.x = __uint_as_float(f2tf32(v[u].x));
                r.y = __uint_as_float(f2tf32(v[u].y));
                r.z = __uint_as_float(f2tf32(v[u].z));
                r.w = __uint_as_float(f2tf32(v[u].w));
                ((float4*)dst)[idx[u]] = r;
            }
        }
    }
}

// ---------------------------------------------------------------------------
// TF32 QKV projection, cp.async 3-stage pipeline, ONE barrier per k-iter.
// Epilogue: Q, K, V all written tf32-rounded (attn consumes bits directly).
// ---------------------------------------------------------------------------
#define BM 128
#define BN 128
#define BK 32
#define ASTRIDE 36
#define BSTRIDE 136
#define G_A_WORDS (BM * ASTRIDE)            // 4608
#define G_B_WORDS (BK * BSTRIDE)            // 4352
#define G_STAGE   (G_A_WORDS + G_B_WORDS)   // 8960 words
#define GEMM_SMEM_BYTES (3 * G_STAGE * 4)   // 107520 B

__global__ __launch_bounds__(256, 2) void qkv_gemm_tf32(
    const float* __restrict__ X,
    const float* __restrict__ Wall,
    const float* __restrict__ bq, const float* __restrict__ bk,
    const float* __restrict__ bv)
{
    extern __shared__ uint32_t smg[];
    const int z = blockIdx.z;
    const float* W = Wall + (size_t)z * HID * HID;
    const float* bias = (z == 0) ? bq : (z == 1) ? bk : bv;
    float* out = (z == 0) ? g_q : (z == 1) ? g_k : g_v;

    const int tid  = threadIdx.x;
    const int lane = tid & 31;
    const int w    = tid >> 5;
    const int wm   = w >> 2;
    const int wn   = w & 3;
    const int m0   = blockIdx.y * BM;
    const int n0   = blockIdx.x * BN;
    const int lg   = lane >> 2;
    const int lt   = lane & 3;
    const int am0  = wm * 64;
    const int bn0  = wn * 32;

    uint32_t smem_base;
    { void* p = smg; smem_base = (uint32_t)__cvta_generic_to_shared(p); }

    int a_r[4], a_c[4], b_r[4], b_c[4];
    #pragma unroll
    for (int p = 0; p < 4; p++) {
        int ia = tid + p * 256;
        a_r[p] = ia >> 3;
        a_c[p] = (ia & 7) * 4;
        b_r[p] = ia >> 5;
        b_c[p] = (ia & 31) * 4;
    }

    auto issue = [&](int stage, int k0) {
        uint32_t ab = smem_base + stage * G_STAGE * 4;
        uint32_t bb2 = ab + G_A_WORDS * 4;
        #pragma unroll
        for (int p = 0; p < 4; p++)
            cp16(ab + (a_r[p] * ASTRIDE + a_c[p]) * 4,
                 X + (size_t)(m0 + a_r[p]) * HID + k0 + a_c[p]);
        #pragma unroll
        for (int p = 0; p < 4; p++)
            cp16(bb2 + (b_r[p] * BSTRIDE + b_c[p]) * 4,
                 W + (size_t)(k0 + b_r[p]) * HID + n0 + b_c[p]);
        cp_commit();
    };

    float c[4][4][4];
    #pragma unroll
    for (int mt = 0; mt < 4; mt++)
        #pragma unroll
        for (int nt = 0; nt < 4; nt++)
            #pragma unroll
            for (int i = 0; i < 4; i++) c[mt][nt][i] = 0.0f;

    issue(0, 0);
    issue(1, BK);

    const int NITER = HID / BK;      // 32
    int st = 0;                      // stage of current compute
    int st2 = 2;                     // stage to fill next

    for (int ki = 0; ki < NITER; ki++) {
        cp_wait1();                  // all groups but newest complete
        __syncthreads();             // also protects buffer st2 (read at ki-1)
        if (ki + 2 < NITER) issue(st2, (ki + 2) * BK);

        const uint32_t* Asp = smg + st * G_STAGE;
        const uint32_t* Bsp = Asp + G_A_WORDS;

        #pragma unroll
        for (int kt = 0; kt < 4; kt++) {
            const int kb = kt * 8;
            uint32_t af[4][4], bf[4][2];
            #pragma unroll
            for (int mt = 0; mt < 4; mt++) {
                int r  = am0 + mt * 16 + lg;
                int cc = kb + lt;
                af[mt][0] = Asp[r * ASTRIDE + cc];
                af[mt][1] = Asp[(r + 8) * ASTRIDE + cc];
                af[mt][2] = Asp[r * ASTRIDE + cc + 4];
                af[mt][3] = Asp[(r + 8) * ASTRIDE + cc + 4];
            }
            #pragma unroll
            for (int nt = 0; nt < 4; nt++) {
                int nn = bn0 + nt * 8 + lg;
                int kk = kb + lt;
                bf[nt][0] = Bsp[kk * BSTRIDE + nn];
                bf[nt][1] = Bsp[(kk + 4) * BSTRIDE + nn];
            }
            #pragma unroll
            for (int mt = 0; mt < 4; mt++)
                #pragma unroll
                for (int nt = 0; nt < 4; nt++)
                    mma_tf32(c[mt][nt], af[mt], bf[nt]);
        }
        st  = (st == 2) ? 0 : st + 1;
        st2 = (st2 == 2) ? 0 : st2 + 1;
    }

    // epilogue: bias add; ALL outputs tf32-rounded; scatter [B,nh,S,hd]
    #pragma unroll
    for (int mt = 0; mt < 4; mt++) {
        int m = m0 + am0 + mt * 16 + lg;
        #pragma unroll
        for (int nt = 0; nt < 4; nt++) {
            int n = n0 + bn0 + nt * 8 + lt * 2;
            float b0 = bias[n], b1 = bias[n + 1];
            int h = n >> 6, d = n & (HD - 1);
            #pragma unroll
            for (int half = 0; half < 2; half++) {
                int mm = m + half * 8;
                int bb = mm >> 10, s = mm & (SEQ - 1);
                float v0 = __uint_as_float(f2tf32(c[mt][nt][half * 2]     + b0));
                float v1 = __uint_as_float(f2tf32(c[mt][nt][half * 2 + 1] + b1));
                *(float2*)(out + (((size_t)bb * NH + h) * SEQ + s) * HD + d) =
                    make_float2(v0, v1);
            }
        }
    }
}

// ---------------------------------------------------------------------------
// Tensor-core flash attention, cp.async 3-stage K/V pipeline, one barrier
// per tile. Q single tf32 (pre-rounded), P single tf32. 128 mma/tile.
// ---------------------------------------------------------------------------
#define KSTRIDE 68
#define VSTRIDE 72
#define PSTRIDE 68
#define SMEM_K  (64 * KSTRIDE)               // 4352 words
#define SMEM_V  (64 * VSTRIDE)               // 4608 words
#define A_STAGE (SMEM_K + SMEM_V)            // 8960 words
#define SMEM_PW (16 * PSTRIDE)               // 1088 words
#define ATTN_SMEM_BYTES ((3 * A_STAGE + 8 * SMEM_PW) * 4)   // 142336 B

__global__ __launch_bounds__(256, 1) void attn_tc(float* __restrict__ out)
{
    extern __shared__ uint32_t sm[];
    const int tid  = threadIdx.x;
    const int lane = tid & 31;
    const int w    = tid >> 5;
    const int lg   = lane >> 2;
    const int lt   = lane & 3;
    uint32_t* Ph = sm + 3 * A_STAGE + w * SMEM_PW;   // per-warp private P

    const int qt = blockIdx.x;
    const int h  = blockIdx.y;
    const int bb = blockIdx.z;
    const size_t bh = (size_t)bb * NH + h;
    const float* Qg = g_q + (bh * SEQ + qt * 128 + w * 16) * HD;
    const float* Kg = g_k + bh * SEQ * HD;
    const float* Vg = g_v + bh * SEQ * HD;

    const int qblk = qt * 2 + (w >> 2);

    uint32_t smem_base;
    { void* p = sm; smem_base = (uint32_t)__cvta_generic_to_shared(p); }

    auto issueKV = [&](int stage, int tile) {
        uint32_t kb2 = smem_base + stage * A_STAGE * 4;
        uint32_t vb2 = kb2 + SMEM_K * 4;
        #pragma unroll
        for (int i = 0; i < 4; i++) {
            int idx = tid + i * 256;
            int r   = idx >> 4;
            int c4  = (idx & 15) * 4;
            cp16(kb2 + (r * KSTRIDE + c4) * 4,
                 Kg + (size_t)tile * 64 * HD + r * HD + c4);
            cp16(vb2 + (r * VSTRIDE + c4) * 4,
                 Vg + (size_t)tile * 64 * HD + r * HD + c4);
        }
        cp_commit();
    };

    // ---- Q fragments (already tf32-rounded in gmem: reload bits) ----
    uint32_t qh[8][4];
    #pragma unroll
    for (int kt = 0; kt < 8; kt++) {
        #pragma unroll
        for (int e = 0; e < 4; e++) {
            int row = lg + (e & 1) * 8;
            int col = kt * 8 + lt + (e >> 1) * 4;
            qh[kt][e] = __float_as_uint(Qg[row * HD + col]);
        }
    }

    float o[8][4];
    #pragma unroll
    for (int nt = 0; nt < 8; nt++)
        #pragma unroll
        for (int e = 0; e < 4; e++) o[nt][e] = 0.0f;
    float l0 = 0.0f, l1 = 0.0f;

    const float C1 = 0.18033688f;            // log2(e)/8
    const int NT = SEQ / 64;                 // 16

    issueKV(0, 0);
    issueKV(1, 1);

    int st = 0, st2 = 2;

    for (int kt64 = 0; kt64 < NT; kt64++) {
        cp_wait1();
        __syncthreads();                      // also frees buffer st2
        if (kt64 + 2 < NT) issueKV(st2, kt64 + 2);

        const uint32_t* Ks = sm + st * A_STAGE;
        const uint32_t* Vs = Ks + SMEM_K;

        // ---- S = Q K^T (single tf32 product) ----
        float sc[8][4];
        #pragma unroll
        for (int nt = 0; nt < 8; nt++)
            #pragma unroll
            for (int e = 0; e < 4; e++) sc[nt][e] = 0.0f;

        #pragma unroll
        for (int kt = 0; kt < 8; kt++) {
            #pragma unroll
            for (int nt = 0; nt < 8; nt++) {
                uint32_t bfr[2];
                bfr[0] = Ks[(nt * 8 + lg) * KSTRIDE + kt * 8 + lt];
                bfr[1] = Ks[(nt * 8 + lg) * KSTRIDE + kt * 8 + lt + 4];
                mma_tf32(sc[nt], qh[kt], bfr);
            }
        }

        // ---- p = exp2(s*log2e/8 - pen2) -> tf32 -> per-warp P smem ----
        const float pen2 = (qblk != kt64) ? 0.72134752f : 0.0f;
        #pragma unroll
        for (int nt = 0; nt < 8; nt++) {
            uint32_t ph2[4];
            #pragma unroll
            for (int e = 0; e < 4; e++) {
                float p = ex2(fmaf(sc[nt][e], C1, -pen2));
                if (e < 2) l0 += p; else l1 += p;
                ph2[e] = f2tf32(p);
            }
            int c0 = nt * 8 + 2 * lt;
            *(uint2*)&Ph[lg * PSTRIDE + c0]       = make_uint2(ph2[0], ph2[1]);
            *(uint2*)&Ph[(lg + 8) * PSTRIDE + c0] = make_uint2(ph2[2], ph2[3]);
        }
        __syncwarp();

        // ---- O += P V ----
        #pragma unroll
        for (int kt = 0; kt < 8; kt++) {
            uint32_t ah[4];
            ah[0] = Ph[lg * PSTRIDE + kt * 8 + lt];
            ah[1] = Ph[(lg + 8) * PSTRIDE + kt * 8 + lt];
            ah[2] = Ph[lg * PSTRIDE + kt * 8 + lt + 4];
            ah[3] = Ph[(lg + 8) * PSTRIDE + kt * 8 + lt + 4];
            #pragma unroll
            for (int nt = 0; nt < 8; nt++) {
                uint32_t bfr[2];
                bfr[0] = Vs[(kt * 8 + lt) * VSTRIDE + nt * 8 + lg];
                bfr[1] = Vs[(kt * 8 + lt + 4) * VSTRIDE + nt * 8 + lg];
                mma_tf32(o[nt], ah, bfr);
            }
        }
        st  = (st == 2) ? 0 : st + 1;
        st2 = (st2 == 2) ? 0 : st2 + 1;
    }

    // ---- normalize and write ----
    l0 += __shfl_xor_sync(0xFFFFFFFFu, l0, 1);
    l0 += __shfl_xor_sync(0xFFFFFFFFu, l0, 2);
    l1 += __shfl_xor_sync(0xFFFFFFFFu, l1, 1);
    l1 += __shfl_xor_sync(0xFFFFFFFFu, l1, 2);
    const float inv0 = 1.0f / l0;
    const float inv1 = 1.0f / l1;

    const int qbase = qt * 128 + w * 16;
    #pragma unroll
    for (int nt = 0; nt < 8; nt++) {
        int d = h * HD + nt * 8 + 2 * lt;
        {
            size_t off = ((size_t)bb * SEQ + qbase + lg) * HID + d;
            *(float2*)(out + off) = make_float2(o[nt][0] * inv0, o[nt][1] * inv0);
        }
        {
            size_t off = ((size_t)bb * SEQ + qbase + lg + 8) * HID + d;
            *(float2*)(out + off) = make_float2(o[nt][2] * inv1, o[nt][3] * inv1);
        }
    }
}

// ---------------------------------------------------------------------------
extern "C" void kernel_launch(void* const* d_in, const int* in_sizes, int n_in,
                              void* d_out, int out_size)
{
    const float* X  = (const float*)d_in[0];
    const float* Wq = (const float*)d_in[1];
    const float* bq = (const float*)d_in[2];
    const float* Wk = (const float*)d_in[3];
    const float* bk = (const float*)d_in[4];
    const float* Wv = (const float*)d_in[5];
    const float* bv = (const float*)d_in[6];

    cudaFuncSetAttribute(qkv_gemm_tf32, cudaFuncAttributeMaxDynamicSharedMemorySize,
                         GEMM_SMEM_BYTES);
    cudaFuncSetAttribute(attn_tc, cudaFuncAttributeMaxDynamicSharedMemorySize,
                         ATTN_SMEM_BYTES);

    float *xr, *wr;
    cudaGetSymbolAddress((void**)&xr, g_xr);
    cudaGetSymbolAddress((void**)&wr, g_wr);

    // prologue: pre-round X + Ws to tf32 (single launch)
    round_all<<<dim3(256, 4), 256>>>(X, Wq, Wk, Wv, xr, wr);

    dim3 g1(HID / BN, MTOT / BM, 3);
    qkv_gemm_tf32<<<g1, 256, GEMM_SMEM_BYTES>>>(xr, wr, bq, bk, bv);

    dim3 g2(SEQ / 128, NH, BATCH);
    attn_tc<<<g2, 256, ATTN_SMEM_BYTES>>>((float*)d_out);
}

// round 9
// speedup vs baseline: 6.4739x; 1.6863x over previous
#include <cuda_runtime.h>
#include <cuda_fp16.h>
#include <cstdint>

#define BATCH 8
#define SEQ   1024
#define HID   1024
#define NH    16
#define HD    64
#define MTOT  (BATCH*SEQ)   // 8192

// Static scratch: fp16 inputs + fp16 projected Q/K/V (V stored transposed).
__device__ __half g_xh[(size_t)MTOT * HID];          // fp16(X)
__device__ __half g_wth[(size_t)3 * HID * HID];      // fp16(W^T), [n][k], 3 stacked
__device__ __half g_qh[(size_t)MTOT * HID];          // Q  [B,nh,S,hd]
__device__ __half g_kh[(size_t)MTOT * HID];          // K  [B,nh,S,hd]
__device__ __half g_vth[(size_t)MTOT * HID];         // V^T [B,nh,hd,S]

__device__ __forceinline__ float ex2(float x) {
    float r;
    asm("ex2.approx.ftz.f32 %0, %1;" : "=f"(r) : "f"(x));
    return r;
}

__device__ __forceinline__ void mma_f16(float c[4], const uint32_t a[4],
                                        const uint32_t b[2]) {
    asm volatile(
        "mma.sync.aligned.m16n8k16.row.col.f32.f16.f16.f32 "
        "{%0,%1,%2,%3}, {%4,%5,%6,%7}, {%8,%9}, {%0,%1,%2,%3};\n"
        : "+f"(c[0]), "+f"(c[1]), "+f"(c[2]), "+f"(c[3])
        : "r"(a[0]), "r"(a[1]), "r"(a[2]), "r"(a[3]), "r"(b[0]), "r"(b[1]));
}

__device__ __forceinline__ void cp16(uint32_t smem_addr, const void* gptr) {
    asm volatile("cp.async.ca.shared.global [%0], [%1], 16;\n"
                 :: "r"(smem_addr), "l"(gptr));
}
__device__ __forceinline__ void cp_commit() {
    asm volatile("cp.async.commit_group;\n");
}
__device__ __forceinline__ void cp_wait1() {
    asm volatile("cp.async.wait_group 1;\n");
}

// ---------------------------------------------------------------------------
// Prologue 1: X fp32 -> fp16 (elementwise). Grid-stride, float4 granularity.
// ---------------------------------------------------------------------------
__global__ __launch_bounds__(256) void conv_x(const float* __restrict__ X,
                                              __half* __restrict__ xh)
{
    const int n4 = MTOT * HID / 4;
    const int stride = gridDim.x * 256;
    for (int i = blockIdx.x * 256 + threadIdx.x; i < n4; i += stride) {
        float4 v = ((const float4*)X)[i];
        __half2 lo = __floats2half2_rn(v.x, v.y);
        __half2 hi = __floats2half2_rn(v.z, v.w);
        ((uint2*)xh)[i] = make_uint2(*(uint32_t*)&lo, *(uint32_t*)&hi);
    }
}

// ---------------------------------------------------------------------------
// Prologue 2: W fp32 [k][n] -> fp16 transposed [n][k]. 32x32 smem tiles.
// blockIdx.z picks Wq/Wk/Wv.
// ---------------------------------------------------------------------------
__global__ __launch_bounds__(256) void transpose_w(
    const float* __restrict__ Wq, const float* __restrict__ Wk,
    const float* __restrict__ Wv, __half* __restrict__ wt)
{
    __shared__ float tile[32][33];
    const float* W = (blockIdx.z == 0) ? Wq : (blockIdx.z == 1) ? Wk : Wv;
    __half* dst = wt + (size_t)blockIdx.z * HID * HID;

    int tx = threadIdx.x & 31, ty = threadIdx.x >> 5;   // 32 x 8
    int x = blockIdx.x * 32 + tx;                        // n (col of W)
    int y = blockIdx.y * 32 + ty;                        // k (row of W)
    #pragma unroll
    for (int j = 0; j < 4; j++)
        tile[ty + 8 * j][tx] = W[(size_t)(y + 8 * j) * HID + x];
    __syncthreads();
    int x2 = blockIdx.y * 32 + tx;                       // k
    int y2 = blockIdx.x * 32 + ty;                       // n
    #pragma unroll
    for (int j = 0; j < 4; j++)
        dst[(size_t)(y2 + 8 * j) * HID + x2] = __float2half_rn(tile[tx][ty + 8 * j]);
}

// ---------------------------------------------------------------------------
// FP16 QKV projection: C = X @ W + b. mma.m16n8k16, cp.async 3-stage.
// BM=BN=128, BK=32 (2 k16 chunks). A tile [128][AW], B tile (W^T) [128][BW],
// word strides AW=BW=20 (fragment reads conflict-free: bank starts
// {0,20,8,28,16,4,24,12} + lt, disjoint runs).
// Epilogue: Q,K fp16 [B,nh,S,hd]; V fp16 TRANSPOSED [B,nh,hd,S].
// ---------------------------------------------------------------------------
#define BM 128
#define BN 128
#define BK 32
#define AW 20                               // words per A row (16 data + 4 pad)
#define BW 20
#define G_A_WORDS (BM * AW)                 // 2560
#define G_B_WORDS (BN * BW)                 // 2560
#define G_STAGE   (G_A_WORDS + G_B_WORDS)   // 5120 words
#define GEMM_SMEM_BYTES (3 * G_STAGE * 4)   // 61440 B

__global__ __launch_bounds__(256, 2) void qkv_gemm_f16(
    const __half* __restrict__ X,      // fp16
    const __half* __restrict__ Wt,     // fp16, transposed, 3 stacked
    const float* __restrict__ bq, const float* __restrict__ bk,
    const float* __restrict__ bv)
{
    extern __shared__ uint32_t smg[];
    const int z = blockIdx.z;
    const __half* W = Wt + (size_t)z * HID * HID;
    const float* bias = (z == 0) ? bq : (z == 1) ? bk : bv;

    const int tid  = threadIdx.x;
    const int lane = tid & 31;
    const int w    = tid >> 5;
    const int wm   = w >> 2;
    const int wn   = w & 3;
    const int m0   = blockIdx.y * BM;
    const int n0   = blockIdx.x * BN;
    const int lg   = lane >> 2;
    const int lt   = lane & 3;
    const int am0  = wm * 64;
    const int bn0  = wn * 32;

    uint32_t smem_base;
    { void* p = smg; smem_base = (uint32_t)__cvta_generic_to_shared(p); }

    // copy slices: 512 cp16 for A (128 rows x 4), 512 for B -> 2+2 per thread
    int r_[2], c_[2];
    #pragma unroll
    for (int p = 0; p < 2; p++) {
        int ia = tid + p * 256;          // 0..511
        r_[p] = ia >> 2;                 // 0..127
        c_[p] = (ia & 3) * 8;            // half offset 0,8,16,24
    }

    auto issue = [&](int stage, int k0) {
        uint32_t ab  = smem_base + stage * G_STAGE * 4;
        uint32_t bb2 = ab + G_A_WORDS * 4;
        #pragma unroll
        for (int p = 0; p < 2; p++)
            cp16(ab + (r_[p] * AW + c_[p] / 2) * 4,
                 X + (size_t)(m0 + r_[p]) * HID + k0 + c_[p]);
        #pragma unroll
        for (int p = 0; p < 2; p++)
            cp16(bb2 + (r_[p] * BW + c_[p] / 2) * 4,
                 W + (size_t)(n0 + r_[p]) * HID + k0 + c_[p]);
        cp_commit();
    };

    float c[4][4][4];
    #pragma unroll
    for (int mt = 0; mt < 4; mt++)
        #pragma unroll
        for (int nt = 0; nt < 4; nt++)
            #pragma unroll
            for (int i = 0; i < 4; i++) c[mt][nt][i] = 0.0f;

    issue(0, 0);
    issue(1, BK);

    const int NITER = HID / BK;      // 32
    int st = 0, st2 = 2;

    for (int ki = 0; ki < NITER; ki++) {
        cp_wait1();
        __syncthreads();
        if (ki + 2 < NITER) issue(st2, (ki + 2) * BK);

        const uint32_t* Asp = smg + st * G_STAGE;
        const uint32_t* Bsp = Asp + G_A_WORDS;

        #pragma unroll
        for (int kc = 0; kc < 2; kc++) {           // 2 chunks of k16
            const int kw = kc * 8;                 // word offset
            uint32_t af[4][4], bf[4][2];
            #pragma unroll
            for (int mt = 0; mt < 4; mt++) {
                int r = am0 + mt * 16 + lg;
                af[mt][0] = Asp[r * AW + kw + lt];
                af[mt][1] = Asp[(r + 8) * AW + kw + lt];
                af[mt][2] = Asp[r * AW + kw + lt + 4];
                af[mt][3] = Asp[(r + 8) * AW + kw + lt + 4];
            }
            #pragma unroll
            for (int nt = 0; nt < 4; nt++) {
                int nn = bn0 + nt * 8 + lg;
                bf[nt][0] = Bsp[nn * BW + kw + lt];
                bf[nt][1] = Bsp[nn * BW + kw + lt + 4];
            }
            #pragma unroll
            for (int mt = 0; mt < 4; mt++)
                #pragma unroll
                for (int nt = 0; nt < 4; nt++)
                    mma_f16(c[mt][nt], af[mt], bf[nt]);
        }
        st  = (st == 2) ? 0 : st + 1;
        st2 = (st2 == 2) ? 0 : st2 + 1;
    }

    // epilogue: bias add, fp16 convert, scatter.
    // Q,K: [B,nh,S,hd] half2 stores. V: transposed [B,nh,hd,S] half stores.
    #pragma unroll
    for (int mt = 0; mt < 4; mt++) {
        int m = m0 + am0 + mt * 16 + lg;
        #pragma unroll
        for (int nt = 0; nt < 4; nt++) {
            int n = n0 + bn0 + nt * 8 + lt * 2;
            float b0 = bias[n], b1 = bias[n + 1];
            int h = n >> 6, d = n & (HD - 1);
            #pragma unroll
            for (int half_ = 0; half_ < 2; half_++) {
                int mm = m + half_ * 8;
                int bb = mm >> 10, s = mm & (SEQ - 1);
                float v0 = c[mt][nt][half_ * 2]     + b0;
                float v1 = c[mt][nt][half_ * 2 + 1] + b1;
                size_t bh = (size_t)bb * NH + h;
                if (z == 2) {
                    // V transposed: row d, col s
                    g_vth[(bh * HD + d)     * SEQ + s] = __float2half_rn(v0);
                    g_vth[(bh * HD + d + 1) * SEQ + s] = __float2half_rn(v1);
                } else {
                    __half2 hv = __floats2half2_rn(v0, v1);
                    __half* out = (z == 0) ? g_qh : g_kh;
                    *(uint32_t*)(out + (bh * SEQ + s) * HD + d) = *(uint32_t*)&hv;
                }
            }
        }
    }
}

// ---------------------------------------------------------------------------
// FP16 tensor-core flash attention, cp.async 3-stage K/V pipeline.
// Grid (SEQ/128, NH, B), 256 threads = 8 warps, warp = 16 q-rows.
// K [key][d] rows; V^T [d][key] rows (both 64x64 fp16, word stride 36 ->
// fragment bank 4*lg+lt, conflict-free). P per-warp [16 rows][32 words].
// 64 mma/tile (32 QK + 32 PV).
// ---------------------------------------------------------------------------
#define KW2 36   // row stride in words (32 data + 4 pad)
#define VW2 36
#define PW2 36
#define SMEM_K  (64 * KW2)                   // 2304 words
#define SMEM_V  (64 * VW2)                   // 2304 words
#define A_STAGE (SMEM_K + SMEM_V)            // 4608 words
#define SMEM_PW (16 * PW2)                   // 576 words
#define ATTN_SMEM_BYTES ((3 * A_STAGE + 8 * SMEM_PW) * 4)   // 73728 B

__global__ __launch_bounds__(256, 1) void attn_tc(float* __restrict__ out)
{
    extern __shared__ uint32_t sm[];
    const int tid  = threadIdx.x;
    const int lane = tid & 31;
    const int w    = tid >> 5;
    const int lg   = lane >> 2;
    const int lt   = lane & 3;
    uint32_t* Ph = sm + 3 * A_STAGE + w * SMEM_PW;   // per-warp private P

    const int qt = blockIdx.x;
    const int h  = blockIdx.y;
    const int bb = blockIdx.z;
    const size_t bh = (size_t)bb * NH + h;
    const __half* Qg = g_qh + (bh * SEQ + qt * 128 + w * 16) * HD;
    const __half* Kg = g_kh + bh * SEQ * HD;
    const __half* Vg = g_vth + bh * HD * SEQ;        // transposed: [d][s]

    const int qblk = qt * 2 + (w >> 2);

    uint32_t smem_base;
    { void* p = sm; smem_base = (uint32_t)__cvta_generic_to_shared(p); }

    auto issueKV = [&](int stage, int tile) {
        uint32_t kb2 = smem_base + stage * A_STAGE * 4;
        uint32_t vb2 = kb2 + SMEM_K * 4;
        #pragma unroll
        for (int i = 0; i < 2; i++) {
            int idx = tid + i * 256;         // 0..511
            int r   = idx >> 3;              // 0..63
            int c8  = (idx & 7) * 8;         // half offset
            cp16(kb2 + (r * KW2 + c8 / 2) * 4,
                 Kg + ((size_t)tile * 64 + r) * HD + c8);
            cp16(vb2 + (r * VW2 + c8 / 2) * 4,
                 Vg + (size_t)r * SEQ + tile * 64 + c8);
        }
        cp_commit();
    };

    // ---- Q fragments (fp16, 4 k16 chunks over HD=64) ----
    uint32_t qf[4][4];
    #pragma unroll
    for (int kc = 0; kc < 4; kc++) {
        #pragma unroll
        for (int e = 0; e < 4; e++) {
            int row = lg + (e & 1) * 8;
            int col = kc * 16 + 2 * lt + (e >> 1) * 8;
            qf[kc][e] = *(const uint32_t*)(Qg + row * HD + col);
        }
    }

    float o[8][4];
    #pragma unroll
    for (int nt = 0; nt < 8; nt++)
        #pragma unroll
        for (int e = 0; e < 4; e++) o[nt][e] = 0.0f;
    float l0 = 0.0f, l1 = 0.0f;

    const float C1 = 0.18033688f;            // log2(e)/8
    const int NT = SEQ / 64;                 // 16

    issueKV(0, 0);
    issueKV(1, 1);

    int st = 0, st2 = 2;

    for (int kt64 = 0; kt64 < NT; kt64++) {
        cp_wait1();
        __syncthreads();
        if (kt64 + 2 < NT) issueKV(st2, kt64 + 2);

        const uint32_t* Ks = sm + st * A_STAGE;
        const uint32_t* Vs = Ks + SMEM_K;

        // ---- S = Q K^T (4 k16 chunks x 8 n-tiles = 32 mmas) ----
        float sc[8][4];
        #pragma unroll
        for (int nt = 0; nt < 8; nt++)
            #pragma unroll
            for (int e = 0; e < 4; e++) sc[nt][e] = 0.0f;

        #pragma unroll
        for (int kc = 0; kc < 4; kc++) {
            const int kw = kc * 8;
            #pragma unroll
            for (int nt = 0; nt < 8; nt++) {
                uint32_t bfr[2];
                bfr[0] = Ks[(nt * 8 + lg) * KW2 + kw + lt];
                bfr[1] = Ks[(nt * 8 + lg) * KW2 + kw + lt + 4];
                mma_f16(sc[nt], qf[kc], bfr);
            }
        }

        // ---- p = exp2(s*log2e/8 - pen2) -> fp16 -> per-warp P smem ----
        const float pen2 = (qblk != kt64) ? 0.72134752f : 0.0f;
        #pragma unroll
        for (int nt = 0; nt < 8; nt++) {
            float p0 = ex2(fmaf(sc[nt][0], C1, -pen2));
            float p1 = ex2(fmaf(sc[nt][1], C1, -pen2));
            float p2 = ex2(fmaf(sc[nt][2], C1, -pen2));
            float p3 = ex2(fmaf(sc[nt][3], C1, -pen2));
            l0 += p0 + p1; l1 += p2 + p3;
            __half2 hA = __floats2half2_rn(p0, p1);   // keys nt*8+2lt, +1
            __half2 hB = __floats2half2_rn(p2, p3);
            Ph[lg * PW2 + nt * 4 + lt]       = *(uint32_t*)&hA;
            Ph[(lg + 8) * PW2 + nt * 4 + lt] = *(uint32_t*)&hB;
        }
        __syncwarp();

        // ---- O += P V (4 k16 chunks over 64 keys x 8 d-tiles) ----
        #pragma unroll
        for (int kc = 0; kc < 4; kc++) {
            const int kw = kc * 8;
            uint32_t ap[4];
            ap[0] = Ph[lg * PW2 + kw + lt];
            ap[1] = Ph[(lg + 8) * PW2 + kw + lt];
            ap[2] = Ph[lg * PW2 + kw + lt + 4];
            ap[3] = Ph[(lg + 8) * PW2 + kw + lt + 4];
            #pragma unroll
            for (int nt = 0; nt < 8; nt++) {
                uint32_t bfr[2];
                bfr[0] = Vs[(nt * 8 + lg) * VW2 + kw + lt];
                bfr[1] = Vs[(nt * 8 + lg) * VW2 + kw + lt + 4];
                mma_f16(o[nt], ap, bfr);
            }
        }
        st  = (st == 2) ? 0 : st + 1;
        st2 = (st2 == 2) ? 0 : st2 + 1;
    }

    // ---- normalize and write ----
    l0 += __shfl_xor_sync(0xFFFFFFFFu, l0, 1);
    l0 += __shfl_xor_sync(0xFFFFFFFFu, l0, 2);
    l1 += __shfl_xor_sync(0xFFFFFFFFu, l1, 1);
    l1 += __shfl_xor_sync(0xFFFFFFFFu, l1, 2);
    const float inv0 = 1.0f / l0;
    const float inv1 = 1.0f / l1;

    const int qbase = qt * 128 + w * 16;
    #pragma unroll
    for (int nt = 0; nt < 8; nt++) {
        int d = h * HD + nt * 8 + 2 * lt;
        {
            size_t off = ((size_t)bb * SEQ + qbase + lg) * HID + d;
            *(float2*)(out + off) = make_float2(o[nt][0] * inv0, o[nt][1] * inv0);
        }
        {
            size_t off = ((size_t)bb * SEQ + qbase + lg + 8) * HID + d;
            *(float2*)(out + off) = make_float2(o[nt][2] * inv1, o[nt][3] * inv1);
        }
    }
}

// ---------------------------------------------------------------------------
extern "C" void kernel_launch(void* const* d_in, const int* in_sizes, int n_in,
                              void* d_out, int out_size)
{
    const float* X  = (const float*)d_in[0];
    const float* Wq = (const float*)d_in[1];
    const float* bq = (const float*)d_in[2];
    const float* Wk = (const float*)d_in[3];
    const float* bk = (const float*)d_in[4];
    const float* Wv = (const float*)d_in[5];
    const float* bv = (const float*)d_in[6];

    cudaFuncSetAttribute(qkv_gemm_f16, cudaFuncAttributeMaxDynamicSharedMemorySize,
                         GEMM_SMEM_BYTES);
    cudaFuncSetAttribute(attn_tc, cudaFuncAttributeMaxDynamicSharedMemorySize,
                         ATTN_SMEM_BYTES);

    __half *xh, *wth;
    cudaGetSymbolAddress((void**)&xh, g_xh);
    cudaGetSymbolAddress((void**)&wth, g_wth);

    // prologue: X -> fp16; W -> fp16 transposed
    conv_x<<<512, 256>>>(X, xh);
    transpose_w<<<dim3(32, 32, 3), 256>>>(Wq, Wk, Wv, wth);

    dim3 g1(HID / BN, MTOT / BM, 3);
    qkv_gemm_f16<<<g1, 256, GEMM_SMEM_BYTES>>>(xh, wth, bq, bk, bv);

    dim3 g2(SEQ / 128, NH, BATCH);
    attn_tc<<<g2, 256, ATTN_SMEM_BYTES>>>((float*)d_out);
}

// round 10
// speedup vs baseline: 6.6656x; 1.0296x over previous
#include <cuda_runtime.h>
#include <cuda_fp16.h>
#include <cstdint>

#define BATCH 8
#define SEQ   1024
#define HID   1024
#define NH    16
#define HD    64
#define MTOT  (BATCH*SEQ)   // 8192

// Static scratch: fp16 inputs + fp16 projected Q/K/V (V stored transposed).
__device__ __half g_xh[(size_t)MTOT * HID];          // fp16(X)
__device__ __half g_wth[(size_t)3 * HID * HID];      // fp16(W^T), [n][k], 3 stacked
__device__ __half g_qh[(size_t)MTOT * HID];          // Q  [B,nh,S,hd]
__device__ __half g_kh[(size_t)MTOT * HID];          // K  [B,nh,S,hd]
__device__ __half g_vth[(size_t)MTOT * HID];         // V^T [B,nh,hd,S]

__device__ __forceinline__ float ex2(float x) {
    float r;
    asm("ex2.approx.ftz.f32 %0, %1;" : "=f"(r) : "f"(x));
    return r;
}

__device__ __forceinline__ void mma_f16(float c[4], const uint32_t a[4],
                                        const uint32_t b[2]) {
    asm volatile(
        "mma.sync.aligned.m16n8k16.row.col.f32.f16.f16.f32 "
        "{%0,%1,%2,%3}, {%4,%5,%6,%7}, {%8,%9}, {%0,%1,%2,%3};\n"
        : "+f"(c[0]), "+f"(c[1]), "+f"(c[2]), "+f"(c[3])
        : "r"(a[0]), "r"(a[1]), "r"(a[2]), "r"(a[3]), "r"(b[0]), "r"(b[1]));
}

__device__ __forceinline__ void cp16(uint32_t smem_addr, const void* gptr) {
    asm volatile("cp.async.ca.shared.global [%0], [%1], 16;\n"
                 :: "r"(smem_addr), "l"(gptr));
}
__device__ __forceinline__ void cp_commit() {
    asm volatile("cp.async.commit_group;\n");
}
__device__ __forceinline__ void cp_wait1() {
    asm volatile("cp.async.wait_group 1;\n");
}

// ---------------------------------------------------------------------------
// Prologue 1: X fp32 -> fp16 (elementwise). Grid-stride, float4 granularity.
// ---------------------------------------------------------------------------
__global__ __launch_bounds__(256) void conv_x(const float* __restrict__ X,
                                              __half* __restrict__ xh)
{
    const int n4 = MTOT * HID / 4;
    const int stride = gridDim.x * 256;
    for (int i = blockIdx.x * 256 + threadIdx.x; i < n4; i += stride) {
        float4 v = ((const float4*)X)[i];
        __half2 lo = __floats2half2_rn(v.x, v.y);
        __half2 hi = __floats2half2_rn(v.z, v.w);
        ((uint2*)xh)[i] = make_uint2(*(uint32_t*)&lo, *(uint32_t*)&hi);
    }
}

// ---------------------------------------------------------------------------
// Prologue 2: W fp32 [k][n] -> fp16 transposed [n][k]. 32x32 smem tiles.
// ---------------------------------------------------------------------------
__global__ __launch_bounds__(256) void transpose_w(
    const float* __restrict__ Wq, const float* __restrict__ Wk,
    const float* __restrict__ Wv, __half* __restrict__ wt)
{
    __shared__ float tile[32][33];
    const float* W = (blockIdx.z == 0) ? Wq : (blockIdx.z == 1) ? Wk : Wv;
    __half* dst = wt + (size_t)blockIdx.z * HID * HID;

    int tx = threadIdx.x & 31, ty = threadIdx.x >> 5;   // 32 x 8
    int x = blockIdx.x * 32 + tx;
    int y = blockIdx.y * 32 + ty;
    #pragma unroll
    for (int j = 0; j < 4; j++)
        tile[ty + 8 * j][tx] = W[(size_t)(y + 8 * j) * HID + x];
    __syncthreads();
    int x2 = blockIdx.y * 32 + tx;
    int y2 = blockIdx.x * 32 + ty;
    #pragma unroll
    for (int j = 0; j < 4; j++)
        dst[(size_t)(y2 + 8 * j) * HID + x2] = __float2half_rn(tile[tx][ty + 8 * j]);
}

// ---------------------------------------------------------------------------
// FP16 QKV projection (unchanged from R9): mma.m16n8k16, cp.async 3-stage.
// ---------------------------------------------------------------------------
#define BM 128
#define BN 128
#define BK 32
#define AW 20
#define BW 20
#define G_A_WORDS (BM * AW)                 // 2560
#define G_B_WORDS (BN * BW)                 // 2560
#define G_STAGE   (G_A_WORDS + G_B_WORDS)   // 5120 words
#define GEMM_SMEM_BYTES (3 * G_STAGE * 4)   // 61440 B

__global__ __launch_bounds__(256, 2) void qkv_gemm_f16(
    const __half* __restrict__ X,
    const __half* __restrict__ Wt,
    const float* __restrict__ bq, const float* __restrict__ bk,
    const float* __restrict__ bv)
{
    extern __shared__ uint32_t smg[];
    const int z = blockIdx.z;
    const __half* W = Wt + (size_t)z * HID * HID;
    const float* bias = (z == 0) ? bq : (z == 1) ? bk : bv;

    const int tid  = threadIdx.x;
    const int lane = tid & 31;
    const int w    = tid >> 5;
    const int wm   = w >> 2;
    const int wn   = w & 3;
    const int m0   = blockIdx.y * BM;
    const int n0   = blockIdx.x * BN;
    const int lg   = lane >> 2;
    const int lt   = lane & 3;
    const int am0  = wm * 64;
    const int bn0  = wn * 32;

    uint32_t smem_base;
    { void* p = smg; smem_base = (uint32_t)__cvta_generic_to_shared(p); }

    int r_[2], c_[2];
    #pragma unroll
    for (int p = 0; p < 2; p++) {
        int ia = tid + p * 256;
        r_[p] = ia >> 2;
        c_[p] = (ia & 3) * 8;
    }

    auto issue = [&](int stage, int k0) {
        uint32_t ab  = smem_base + stage * G_STAGE * 4;
        uint32_t bb2 = ab + G_A_WORDS * 4;
        #pragma unroll
        for (int p = 0; p < 2; p++)
            cp16(ab + (r_[p] * AW + c_[p] / 2) * 4,
                 X + (size_t)(m0 + r_[p]) * HID + k0 + c_[p]);
        #pragma unroll
        for (int p = 0; p < 2; p++)
            cp16(bb2 + (r_[p] * BW + c_[p] / 2) * 4,
                 W + (size_t)(n0 + r_[p]) * HID + k0 + c_[p]);
        cp_commit();
    };

    float c[4][4][4];
    #pragma unroll
    for (int mt = 0; mt < 4; mt++)
        #pragma unroll
        for (int nt = 0; nt < 4; nt++)
            #pragma unroll
            for (int i = 0; i < 4; i++) c[mt][nt][i] = 0.0f;

    issue(0, 0);
    issue(1, BK);

    const int NITER = HID / BK;
    int st = 0, st2 = 2;

    for (int ki = 0; ki < NITER; ki++) {
        cp_wait1();
        __syncthreads();
        if (ki + 2 < NITER) issue(st2, (ki + 2) * BK);

        const uint32_t* Asp = smg + st * G_STAGE;
        const uint32_t* Bsp = Asp + G_A_WORDS;

        #pragma unroll
        for (int kc = 0; kc < 2; kc++) {
            const int kw = kc * 8;
            uint32_t af[4][4], bf[4][2];
            #pragma unroll
            for (int mt = 0; mt < 4; mt++) {
                int r = am0 + mt * 16 + lg;
                af[mt][0] = Asp[r * AW + kw + lt];
                af[mt][1] = Asp[(r + 8) * AW + kw + lt];
                af[mt][2] = Asp[r * AW + kw + lt + 4];
                af[mt][3] = Asp[(r + 8) * AW + kw + lt + 4];
            }
            #pragma unroll
            for (int nt = 0; nt < 4; nt++) {
                int nn = bn0 + nt * 8 + lg;
                bf[nt][0] = Bsp[nn * BW + kw + lt];
                bf[nt][1] = Bsp[nn * BW + kw + lt + 4];
            }
            #pragma unroll
            for (int mt = 0; mt < 4; mt++)
                #pragma unroll
                for (int nt = 0; nt < 4; nt++)
                    mma_f16(c[mt][nt], af[mt], bf[nt]);
        }
        st  = (st == 2) ? 0 : st + 1;
        st2 = (st2 == 2) ? 0 : st2 + 1;
    }

    #pragma unroll
    for (int mt = 0; mt < 4; mt++) {
        int m = m0 + am0 + mt * 16 + lg;
        #pragma unroll
        for (int nt = 0; nt < 4; nt++) {
            int n = n0 + bn0 + nt * 8 + lt * 2;
            float b0 = bias[n], b1 = bias[n + 1];
            int h = n >> 6, d = n & (HD - 1);
            #pragma unroll
            for (int half_ = 0; half_ < 2; half_++) {
                int mm = m + half_ * 8;
                int bb = mm >> 10, s = mm & (SEQ - 1);
                float v0 = c[mt][nt][half_ * 2]     + b0;
                float v1 = c[mt][nt][half_ * 2 + 1] + b1;
                size_t bh = (size_t)bb * NH + h;
                if (z == 2) {
                    g_vth[(bh * HD + d)     * SEQ + s] = __float2half_rn(v0);
                    g_vth[(bh * HD + d + 1) * SEQ + s] = __float2half_rn(v1);
                } else {
                    __half2 hv = __floats2half2_rn(v0, v1);
                    __half* out = (z == 0) ? g_qh : g_kh;
                    *(uint32_t*)(out + (bh * SEQ + s) * HD + d) = *(uint32_t*)&hv;
                }
            }
        }
    }
}

// ---------------------------------------------------------------------------
// FP16 flash attention — now 2 CTAs/SM (__launch_bounds__(256,2)):
// 16 warps/SM for latency hiding (R9: tensor=44%, issue=36.5% at 1 CTA/SM).
// Smem 73728 B/CTA x 2 = 147 KB < 228 KB cap.
// ---------------------------------------------------------------------------
#define KW2 36
#define VW2 36
#define PW2 36
#define SMEM_K  (64 * KW2)                   // 2304 words
#define SMEM_V  (64 * VW2)                   // 2304 words
#define A_STAGE (SMEM_K + SMEM_V)            // 4608 words
#define SMEM_PW (16 * PW2)                   // 576 words
#define ATTN_SMEM_BYTES ((3 * A_STAGE + 8 * SMEM_PW) * 4)   // 73728 B

__global__ __launch_bounds__(256, 2) void attn_tc(float* __restrict__ out)
{
    extern __shared__ uint32_t sm[];
    const int tid  = threadIdx.x;
    const int lane = tid & 31;
    const int w    = tid >> 5;
    const int lg   = lane >> 2;
    const int lt   = lane & 3;
    uint32_t* Ph = sm + 3 * A_STAGE + w * SMEM_PW;

    const int qt = blockIdx.x;
    const int h  = blockIdx.y;
    const int bb = blockIdx.z;
    const size_t bh = (size_t)bb * NH + h;
    const __half* Qg = g_qh + (bh * SEQ + qt * 128 + w * 16) * HD;
    const __half* Kg = g_kh + bh * SEQ * HD;
    const __half* Vg = g_vth + bh * HD * SEQ;

    const int qblk = qt * 2 + (w >> 2);

    uint32_t smem_base;
    { void* p = sm; smem_base = (uint32_t)__cvta_generic_to_shared(p); }

    auto issueKV = [&](int stage, int tile) {
        uint32_t kb2 = smem_base + stage * A_STAGE * 4;
        uint32_t vb2 = kb2 + SMEM_K * 4;
        #pragma unroll
        for (int i = 0; i < 2; i++) {
            int idx = tid + i * 256;
            int r   = idx >> 3;
            int c8  = (idx & 7) * 8;
            cp16(kb2 + (r * KW2 + c8 / 2) * 4,
                 Kg + ((size_t)tile * 64 + r) * HD + c8);
            cp16(vb2 + (r * VW2 + c8 / 2) * 4,
                 Vg + (size_t)r * SEQ + tile * 64 + c8);
        }
        cp_commit();
    };

    uint32_t qf[4][4];
    #pragma unroll
    for (int kc = 0; kc < 4; kc++) {
        #pragma unroll
        for (int e = 0; e < 4; e++) {
            int row = lg + (e & 1) * 8;
            int col = kc * 16 + 2 * lt + (e >> 1) * 8;
            qf[kc][e] = *(const uint32_t*)(Qg + row * HD + col);
        }
    }

    float o[8][4];
    #pragma unroll
    for (int nt = 0; nt < 8; nt++)
        #pragma unroll
        for (int e = 0; e < 4; e++) o[nt][e] = 0.0f;
    float l0 = 0.0f, l1 = 0.0f;

    const float C1 = 0.18033688f;
    const int NT = SEQ / 64;

    issueKV(0, 0);
    issueKV(1, 1);

    int st = 0, st2 = 2;

    for (int kt64 = 0; kt64 < NT; kt64++) {
        cp_wait1();
        __syncthreads();
        if (kt64 + 2 < NT) issueKV(st2, kt64 + 2);

        const uint32_t* Ks = sm + st * A_STAGE;
        const uint32_t* Vs = Ks + SMEM_K;

        float sc[8][4];
        #pragma unroll
        for (int nt = 0; nt < 8; nt++)
            #pragma unroll
            for (int e = 0; e < 4; e++) sc[nt][e] = 0.0f;

        #pragma unroll
        for (int kc = 0; kc < 4; kc++) {
            const int kw = kc * 8;
            #pragma unroll
            for (int nt = 0; nt < 8; nt++) {
                uint32_t bfr[2];
                bfr[0] = Ks[(nt * 8 + lg) * KW2 + kw + lt];
                bfr[1] = Ks[(nt * 8 + lg) * KW2 + kw + lt + 4];
                mma_f16(sc[nt], qf[kc], bfr);
            }
        }

        const float pen2 = (qblk != kt64) ? 0.72134752f : 0.0f;
        #pragma unroll
        for (int nt = 0; nt < 8; nt++) {
            float p0 = ex2(fmaf(sc[nt][0], C1, -pen2));
            float p1 = ex2(fmaf(sc[nt][1], C1, -pen2));
            float p2 = ex2(fmaf(sc[nt][2], C1, -pen2));
            float p3 = ex2(fmaf(sc[nt][3], C1, -pen2));
            l0 += p0 + p1; l1 += p2 + p3;
            __half2 hA = __floats2half2_rn(p0, p1);
            __half2 hB = __floats2half2_rn(p2, p3);
            Ph[lg * PW2 + nt * 4 + lt]       = *(uint32_t*)&hA;
            Ph[(lg + 8) * PW2 + nt * 4 + lt] = *(uint32_t*)&hB;
        }
        __syncwarp();

        #pragma unroll
        for (int kc = 0; kc < 4; kc++) {
            const int kw = kc * 8;
            uint32_t ap[4];
            ap[0] = Ph[lg * PW2 + kw + lt];
            ap[1] = Ph[(lg + 8) * PW2 + kw + lt];
            ap[2] = Ph[lg * PW2 + kw + lt + 4];
            ap[3] = Ph[(lg + 8) * PW2 + kw + lt + 4];
            #pragma unroll
            for (int nt = 0; nt < 8; nt++) {
                uint32_t bfr[2];
                bfr[0] = Vs[(nt * 8 + lg) * VW2 + kw + lt];
                bfr[1] = Vs[(nt * 8 + lg) * VW2 + kw + lt + 4];
                mma_f16(o[nt], ap, bfr);
            }
        }
        st  = (st == 2) ? 0 : st + 1;
        st2 = (st2 == 2) ? 0 : st2 + 1;
    }

    l0 += __shfl_xor_sync(0xFFFFFFFFu, l0, 1);
    l0 += __shfl_xor_sync(0xFFFFFFFFu, l0, 2);
    l1 += __shfl_xor_sync(0xFFFFFFFFu, l1, 1);
    l1 += __shfl_xor_sync(0xFFFFFFFFu, l1, 2);
    const float inv0 = 1.0f / l0;
    const float inv1 = 1.0f / l1;

    const int qbase = qt * 128 + w * 16;
    #pragma unroll
    for (int nt = 0; nt < 8; nt++) {
        int d = h * HD + nt * 8 + 2 * lt;
        {
            size_t off = ((size_t)bb * SEQ + qbase + lg) * HID + d;
            *(float2*)(out + off) = make_float2(o[nt][0] * inv0, o[nt][1] * inv0);
        }
        {
            size_t off = ((size_t)bb * SEQ + qbase + lg + 8) * HID + d;
            *(float2*)(out + off) = make_float2(o[nt][2] * inv1, o[nt][3] * inv1);
        }
    }
}

// ---------------------------------------------------------------------------
extern "C" void kernel_launch(void* const* d_in, const int* in_sizes, int n_in,
                              void* d_out, int out_size)
{
    const float* X  = (const float*)d_in[0];
    const float* Wq = (const float*)d_in[1];
    const float* bq = (const float*)d_in[2];
    const float* Wk = (const float*)d_in[3];
    const float* bk = (const float*)d_in[4];
    const float* Wv = (const float*)d_in[5];
    const float* bv = (const float*)d_in[6];

    cudaFuncSetAttribute(qkv_gemm_f16, cudaFuncAttributeMaxDynamicSharedMemorySize,
                         GEMM_SMEM_BYTES);
    cudaFuncSetAttribute(attn_tc, cudaFuncAttributeMaxDynamicSharedMemorySize,
                         ATTN_SMEM_BYTES);

    __half *xh, *wth;
    cudaGetSymbolAddress((void**)&xh, g_xh);
    cudaGetSymbolAddress((void**)&wth, g_wth);

    conv_x<<<512, 256>>>(X, xh);
    transpose_w<<<dim3(32, 32, 3), 256>>>(Wq, Wk, Wv, wth);

    dim3 g1(HID / BN, MTOT / BM, 3);
    qkv_gemm_f16<<<g1, 256, GEMM_SMEM_BYTES>>>(xh, wth, bq, bk, bv);

    dim3 g2(SEQ / 128, NH, BATCH);
    attn_tc<<<g2, 256, ATTN_SMEM_BYTES>>>((float*)d_out);
}

// round 16
// speedup vs baseline: 6.7520x; 1.0130x over previous
#include <cuda_runtime.h>
#include <cuda_fp16.h>
#include <cstdint>

#define BATCH 8
#define SEQ   1024
#define HID   1024
#define NH    16
#define HD    64
#define MTOT  (BATCH*SEQ)   // 8192

// Static scratch: fp16 inputs + fp16 projected Q/K/V (V stored transposed).
__device__ __half g_xh[(size_t)MTOT * HID];          // fp16(X)
__device__ __half g_wth[(size_t)3 * HID * HID];      // fp16(W^T), [n][k], 3 stacked
__device__ __half g_qh[(size_t)MTOT * HID];          // Q  [B,nh,S,hd]
__device__ __half g_kh[(size_t)MTOT * HID];          // K  [B,nh,S,hd]
__device__ __half g_vth[(size_t)MTOT * HID];         // V^T [B,nh,hd,S]

__device__ __forceinline__ float ex2(float x) {
    float r;
    asm("ex2.approx.ftz.f32 %0, %1;" : "=f"(r) : "f"(x));
    return r;
}

__device__ __forceinline__ void mma_f16(float c[4], const uint32_t a[4],
                                        const uint32_t b[2]) {
    asm volatile(
        "mma.sync.aligned.m16n8k16.row.col.f32.f16.f16.f32 "
        "{%0,%1,%2,%3}, {%4,%5,%6,%7}, {%8,%9}, {%0,%1,%2,%3};\n"
        : "+f"(c[0]), "+f"(c[1]), "+f"(c[2]), "+f"(c[3])
        : "r"(a[0]), "r"(a[1]), "r"(a[2]), "r"(a[3]), "r"(b[0]), "r"(b[1]));
}

__device__ __forceinline__ void cp16(uint32_t smem_addr, const void* gptr) {
    asm volatile("cp.async.ca.shared.global [%0], [%1], 16;\n"
                 :: "r"(smem_addr), "l"(gptr));
}
__device__ __forceinline__ void cp_commit() {
    asm volatile("cp.async.commit_group;\n");
}
__device__ __forceinline__ void cp_wait0() {
    asm volatile("cp.async.wait_group 0;\n");
}
__device__ __forceinline__ void cp_wait1() {
    asm volatile("cp.async.wait_group 1;\n");
}

// ---------------------------------------------------------------------------
// Prologue 1: X fp32 -> fp16 (elementwise).
// ---------------------------------------------------------------------------
__global__ __launch_bounds__(256) void conv_x(const float* __restrict__ X,
                                              __half* __restrict__ xh)
{
    const int n4 = MTOT * HID / 4;
    const int stride = gridDim.x * 256;
    for (int i = blockIdx.x * 256 + threadIdx.x; i < n4; i += stride) {
        float4 v = ((const float4*)X)[i];
        __half2 lo = __floats2half2_rn(v.x, v.y);
        __half2 hi = __floats2half2_rn(v.z, v.w);
        ((uint2*)xh)[i] = make_uint2(*(uint32_t*)&lo, *(uint32_t*)&hi);
    }
}

// ---------------------------------------------------------------------------
// Prologue 2: W fp32 [k][n] -> fp16 transposed [n][k].
// ---------------------------------------------------------------------------
__global__ __launch_bounds__(256) void transpose_w(
    const float* __restrict__ Wq, const float* __restrict__ Wk,
    const float* __restrict__ Wv, __half* __restrict__ wt)
{
    __shared__ float tile[32][33];
    const float* W = (blockIdx.z == 0) ? Wq : (blockIdx.z == 1) ? Wk : Wv;
    __half* dst = wt + (size_t)blockIdx.z * HID * HID;

    int tx = threadIdx.x & 31, ty = threadIdx.x >> 5;
    int x = blockIdx.x * 32 + tx;
    int y = blockIdx.y * 32 + ty;
    #pragma unroll
    for (int j = 0; j < 4; j++)
        tile[ty + 8 * j][tx] = W[(size_t)(y + 8 * j) * HID + x];
    __syncthreads();
    int x2 = blockIdx.y * 32 + tx;
    int y2 = blockIdx.x * 32 + ty;
    #pragma unroll
    for (int j = 0; j < 4; j++)
        dst[(size_t)(y2 + 8 * j) * HID + x2] = __float2half_rn(tile[tx][ty + 8 * j]);
}

// ---------------------------------------------------------------------------
// FP16 QKV projection (R10 version + final-iter wait fix).
// ---------------------------------------------------------------------------
#define BM 128
#define BN 128
#define BK 32
#define AW 20
#define BW 20
#define G_A_WORDS (BM * AW)                 // 2560
#define G_B_WORDS (BN * BW)                 // 2560
#define G_STAGE   (G_A_WORDS + G_B_WORDS)   // 5120 words
#define GEMM_SMEM_BYTES (3 * G_STAGE * 4)   // 61440 B

__global__ __launch_bounds__(256, 2) void qkv_gemm_f16(
    const __half* __restrict__ X,
    const __half* __restrict__ Wt,
    const float* __restrict__ bq, const float* __restrict__ bk,
    const float* __restrict__ bv)
{
    extern __shared__ uint32_t smg[];
    const int z = blockIdx.z;
    const __half* W = Wt + (size_t)z * HID * HID;
    const float* bias = (z == 0) ? bq : (z == 1) ? bk : bv;

    const int tid  = threadIdx.x;
    const int lane = tid & 31;
    const int w    = tid >> 5;
    const int wm   = w >> 2;
    const int wn   = w & 3;
    const int m0   = blockIdx.y * BM;
    const int n0   = blockIdx.x * BN;
    const int lg   = lane >> 2;
    const int lt   = lane & 3;
    const int am0  = wm * 64;
    const int bn0  = wn * 32;

    uint32_t smem_base;
    { void* p = smg; smem_base = (uint32_t)__cvta_generic_to_shared(p); }

    int r_[2], c_[2];
    #pragma unroll
    for (int p = 0; p < 2; p++) {
        int ia = tid + p * 256;
        r_[p] = ia >> 2;
        c_[p] = (ia & 3) * 8;
    }

    auto issue = [&](int stage, int k0) {
        uint32_t ab  = smem_base + stage * G_STAGE * 4;
        uint32_t bb2 = ab + G_A_WORDS * 4;
        #pragma unroll
        for (int p = 0; p < 2; p++)
            cp16(ab + (r_[p] * AW + c_[p] / 2) * 4,
                 X + (size_t)(m0 + r_[p]) * HID + k0 + c_[p]);
        #pragma unroll
        for (int p = 0; p < 2; p++)
            cp16(bb2 + (r_[p] * BW + c_[p] / 2) * 4,
                 W + (size_t)(n0 + r_[p]) * HID + k0 + c_[p]);
        cp_commit();
    };

    float c[4][4][4];
    #pragma unroll
    for (int mt = 0; mt < 4; mt++)
        #pragma unroll
        for (int nt = 0; nt < 4; nt++)
            #pragma unroll
            for (int i = 0; i < 4; i++) c[mt][nt][i] = 0.0f;

    issue(0, 0);
    issue(1, BK);

    const int NITER = HID / BK;
    int st = 0, st2 = 2;

    for (int ki = 0; ki < NITER; ki++) {
        if (ki == NITER - 1) cp_wait0(); else cp_wait1();
        __syncthreads();
        if (ki + 2 < NITER) issue(st2, (ki + 2) * BK);

        const uint32_t* Asp = smg + st * G_STAGE;
        const uint32_t* Bsp = Asp + G_A_WORDS;

        #pragma unroll
        for (int kc = 0; kc < 2; kc++) {
            const int kw = kc * 8;
            uint32_t af[4][4], bf[4][2];
            #pragma unroll
            for (int mt = 0; mt < 4; mt++) {
                int r = am0 + mt * 16 + lg;
                af[mt][0] = Asp[r * AW + kw + lt];
                af[mt][1] = Asp[(r + 8) * AW + kw + lt];
                af[mt][2] = Asp[r * AW + kw + lt + 4];
                af[mt][3] = Asp[(r + 8) * AW + kw + lt + 4];
            }
            #pragma unroll
            for (int nt = 0; nt < 4; nt++) {
                int nn = bn0 + nt * 8 + lg;
                bf[nt][0] = Bsp[nn * BW + kw + lt];
                bf[nt][1] = Bsp[nn * BW + kw + lt + 4];
            }
            #pragma unroll
            for (int mt = 0; mt < 4; mt++)
                #pragma unroll
                for (int nt = 0; nt < 4; nt++)
                    mma_f16(c[mt][nt], af[mt], bf[nt]);
        }
        st  = (st == 2) ? 0 : st + 1;
        st2 = (st2 == 2) ? 0 : st2 + 1;
    }

    #pragma unroll
    for (int mt = 0; mt < 4; mt++) {
        int m = m0 + am0 + mt * 16 + lg;
        #pragma unroll
        for (int nt = 0; nt < 4; nt++) {
            int n = n0 + bn0 + nt * 8 + lt * 2;
            float b0 = bias[n], b1 = bias[n + 1];
            int h = n >> 6, d = n & (HD - 1);
            #pragma unroll
            for (int half_ = 0; half_ < 2; half_++) {
                int mm = m + half_ * 8;
                int bb = mm >> 10, s = mm & (SEQ - 1);
                float v0 = c[mt][nt][half_ * 2]     + b0;
                float v1 = c[mt][nt][half_ * 2 + 1] + b1;
                size_t bh = (size_t)bb * NH + h;
                if (z == 2) {
                    g_vth[(bh * HD + d)     * SEQ + s] = __float2half_rn(v0);
                    g_vth[(bh * HD + d + 1) * SEQ + s] = __float2half_rn(v1);
                } else {
                    __half2 hv = __floats2half2_rn(v0, v1);
                    __half* out = (z == 0) ? g_qh : g_kh;
                    *(uint32_t*)(out + (bh * SEQ + s) * HD + d) = *(uint32_t*)&hv;
                }
            }
        }
    }
}

// ---------------------------------------------------------------------------
// FP16 flash attention, 32 q-rows per warp (m32 warp tile): every K/V
// fragment LDS feeds TWO mmas -> crossbar traffic halved vs R10 (L1 was
// 74.9% and binding). 128 threads = 4 warps x 32 rows = 128 rows/CTA.
// __launch_bounds__(128,3): 12 warps/SM, smem 72KB x 3 = 216KB.
// ---------------------------------------------------------------------------
#define KW2 36
#define VW2 36
#define PW2 36
#define SMEM_K  (64 * KW2)                   // 2304 words
#define SMEM_V  (64 * VW2)                   // 2304 words
#define A_STAGE (SMEM_K + SMEM_V)            // 4608 words
#define SMEM_PW (32 * PW2)                   // 1152 words per warp (32 rows)
#define ATTN_SMEM_BYTES ((3 * A_STAGE + 4 * SMEM_PW) * 4)   // 73728 B

__global__ __launch_bounds__(128, 3) void attn_tc(float* __restrict__ out)
{
    extern __shared__ uint32_t sm[];
    const int tid  = threadIdx.x;
    const int lane = tid & 31;
    const int w    = tid >> 5;               // 0..3
    const int lg   = lane >> 2;
    const int lt   = lane & 3;
    uint32_t* Ph = sm + 3 * A_STAGE + w * SMEM_PW;

    const int qt = blockIdx.x;               // 0..7
    const int h  = blockIdx.y;
    const int bb = blockIdx.z;
    const size_t bh = (size_t)bb * NH + h;
    const __half* Qg = g_qh + (bh * SEQ + qt * 128 + w * 32) * HD;
    const __half* Kg = g_kh + bh * SEQ * HD;
    const __half* Vg = g_vth + bh * HD * SEQ;

    const int qblk = qt * 2 + (w >> 1);      // warp covers rows inside one 64-block

    uint32_t smem_base;
    { void* p = sm; smem_base = (uint32_t)__cvta_generic_to_shared(p); }

    auto issueKV = [&](int stage, int tile) {
        uint32_t kb2 = smem_base + stage * A_STAGE * 4;
        uint32_t vb2 = kb2 + SMEM_K * 4;
        #pragma unroll
        for (int i = 0; i < 8; i++) {
            int idx = tid + i * 128;          // 0..1023
            if (idx < 512) {
                int r = idx >> 3, c8 = (idx & 7) * 8;
                cp16(kb2 + (r * KW2 + c8 / 2) * 4,
                     Kg + ((size_t)tile * 64 + r) * HD + c8);
            } else {
                int j = idx - 512;
                int r = j >> 3, c8 = (j & 7) * 8;
                cp16(vb2 + (r * VW2 + c8 / 2) * 4,
                     Vg + (size_t)r * SEQ + tile * 64 + c8);
            }
        }
        cp_commit();
    };

    // ---- Q fragments: 2 m16 tiles x 4 k16 chunks ----
    uint32_t qf[2][4][4];
    #pragma unroll
    for (int mt = 0; mt < 2; mt++)
        #pragma unroll
        for (int kc = 0; kc < 4; kc++)
            #pragma unroll
            for (int e = 0; e < 4; e++) {
                int row = mt * 16 + lg + (e & 1) * 8;
                int col = kc * 16 + 2 * lt + (e >> 1) * 8;
                qf[mt][kc][e] = *(const uint32_t*)(Qg + row * HD + col);
            }

    float o[2][8][4];
    #pragma unroll
    for (int mt = 0; mt < 2; mt++)
        #pragma unroll
        for (int nt = 0; nt < 8; nt++)
            #pragma unroll
            for (int e = 0; e < 4; e++) o[mt][nt][e] = 0.0f;
    float lsum[2][2] = {{0.0f, 0.0f}, {0.0f, 0.0f}};

    const float C1 = 0.18033688f;            // log2(e)/8
    const int NT = SEQ / 64;                 // 16

    issueKV(0, 0);
    issueKV(1, 1);

    int st = 0, st2 = 2;

    for (int kt64 = 0; kt64 < NT; kt64++) {
        if (kt64 == NT - 1) cp_wait0(); else cp_wait1();
        __syncthreads();
        if (kt64 + 2 < NT) issueKV(st2, kt64 + 2);

        const uint32_t* Ks = sm + st * A_STAGE;
        const uint32_t* Vs = Ks + SMEM_K;
        const float pen2 = (qblk != kt64) ? 0.72134752f : 0.0f;

        // ---- S = Q K^T + exp, in two key-halves (limits sc registers) ----
        #pragma unroll
        for (int half_ = 0; half_ < 2; half_++) {
            float sc[2][4][4];
            #pragma unroll
            for (int mt = 0; mt < 2; mt++)
                #pragma unroll
                for (int j = 0; j < 4; j++)
                    #pragma unroll
                    for (int e = 0; e < 4; e++) sc[mt][j][e] = 0.0f;

            #pragma unroll
            for (int kc = 0; kc < 4; kc++) {
                const int kw = kc * 8;
                #pragma unroll
                for (int j = 0; j < 4; j++) {
                    int nt = half_ * 4 + j;
                    uint32_t bfr[2];
                    bfr[0] = Ks[(nt * 8 + lg) * KW2 + kw + lt];
                    bfr[1] = Ks[(nt * 8 + lg) * KW2 + kw + lt + 4];
                    mma_f16(sc[0][j], qf[0][kc], bfr);   // fragment reused
                    mma_f16(sc[1][j], qf[1][kc], bfr);   // for both m16 tiles
                }
            }

            #pragma unroll
            for (int mt = 0; mt < 2; mt++)
                #pragma unroll
                for (int j = 0; j < 4; j++) {
                    int nt = half_ * 4 + j;
                    float p0 = ex2(fmaf(sc[mt][j][0], C1, -pen2));
                    float p1 = ex2(fmaf(sc[mt][j][1], C1, -pen2));
                    float p2 = ex2(fmaf(sc[mt][j][2], C1, -pen2));
                    float p3 = ex2(fmaf(sc[mt][j][3], C1, -pen2));
                    lsum[mt][0] += p0 + p1;
                    lsum[mt][1] += p2 + p3;
                    __half2 hA = __floats2half2_rn(p0, p1);
                    __half2 hB = __floats2half2_rn(p2, p3);
                    Ph[(mt * 16 + lg) * PW2 + nt * 4 + lt]       = *(uint32_t*)&hA;
                    Ph[(mt * 16 + lg + 8) * PW2 + nt * 4 + lt]   = *(uint32_t*)&hB;
                }
        }
        __syncwarp();

        // ---- O += P V (V fragment reused for both m16 tiles) ----
        #pragma unroll
        for (int kc = 0; kc < 4; kc++) {
            const int kw = kc * 8;
            uint32_t ap[2][4];
            #pragma unroll
            for (int mt = 0; mt < 2; mt++) {
                ap[mt][0] = Ph[(mt * 16 + lg) * PW2 + kw + lt];
                ap[mt][1] = Ph[(mt * 16 + lg + 8) * PW2 + kw + lt];
                ap[mt][2] = Ph[(mt * 16 + lg) * PW2 + kw + lt + 4];
                ap[mt][3] = Ph[(mt * 16 + lg + 8) * PW2 + kw + lt + 4];
            }
            #pragma unroll
            for (int nt = 0; nt < 8; nt++) {
                uint32_t bfr[2];
                bfr[0] = Vs[(nt * 8 + lg) * VW2 + kw + lt];
                bfr[1] = Vs[(nt * 8 + lg) * VW2 + kw + lt + 4];
                mma_f16(o[0][nt], ap[0], bfr);
                mma_f16(o[1][nt], ap[1], bfr);
            }
        }
        st  = (st == 2) ? 0 : st + 1;
        st2 = (st2 == 2) ? 0 : st2 + 1;
    }

    // ---- normalize and write ----
    #pragma unroll
    for (int mt = 0; mt < 2; mt++)
        #pragma unroll
        for (int i = 0; i < 2; i++) {
            lsum[mt][i] += __shfl_xor_sync(0xFFFFFFFFu, lsum[mt][i], 1);
            lsum[mt][i] += __shfl_xor_sync(0xFFFFFFFFu, lsum[mt][i], 2);
        }

    #pragma unroll
    for (int mt = 0; mt < 2; mt++) {
        const float inv0 = 1.0f / lsum[mt][0];
        const float inv1 = 1.0f / lsum[mt][1];
        const int qbase = qt * 128 + w * 32 + mt * 16;
        #pragma unroll
        for (int nt = 0; nt < 8; nt++) {
            int d = h * HD + nt * 8 + 2 * lt;
            {
                size_t off = ((size_t)bb * SEQ + qbase + lg) * HID + d;
                *(float2*)(out + off) =
                    make_float2(o[mt][nt][0] * inv0, o[mt][nt][1] * inv0);
            }
            {
                size_t off = ((size_t)bb * SEQ + qbase + lg + 8) * HID + d;
                *(float2*)(out + off) =
                    make_float2(o[mt][nt][2] * inv1, o[mt][nt][3] * inv1);
            }
        }
    }
}

// ---------------------------------------------------------------------------
extern "C" void kernel_launch(void* const* d_in, const int* in_sizes, int n_in,
                              void* d_out, int out_size)
{
    const float* X  = (const float*)d_in[0];
    const float* Wq = (const float*)d_in[1];
    const float* bq = (const float*)d_in[2];
    const float* Wk = (const float*)d_in[3];
    const float* bk = (const float*)d_in[4];
    const float* Wv = (const float*)d_in[5];
    const float* bv = (const float*)d_in[6];

    cudaFuncSetAttribute(qkv_gemm_f16, cudaFuncAttributeMaxDynamicSharedMemorySize,
                         GEMM_SMEM_BYTES);
    cudaFuncSetAttribute(attn_tc, cudaFuncAttributeMaxDynamicSharedMemorySize,
                         ATTN_SMEM_BYTES);

    __half *xh, *wth;
    cudaGetSymbolAddress((void**)&xh, g_xh);
    cudaGetSymbolAddress((void**)&wth, g_wth);

    conv_x<<<512, 256>>>(X, xh);
    transpose_w<<<dim3(32, 32, 3), 256>>>(Wq, Wk, Wv, wth);

    dim3 g1(HID / BN, MTOT / BM, 3);
    qkv_gemm_f16<<<g1, 256, GEMM_SMEM_BYTES>>>(xh, wth, bq, bk, bv);

    dim3 g2(SEQ / 128, NH, BATCH);      // 1024 CTAs, 128 threads each
    attn_tc<<<g2, 128, ATTN_SMEM_BYTES>>>((float*)d_out);
}

// round 17
// speedup vs baseline: 7.7862x; 1.1532x over previous
#include <cuda_runtime.h>
#include <cuda_fp16.h>
#include <cstdint>

#define BATCH 8
#define SEQ   1024
#define HID   1024
#define NH    16
#define HD    64
#define MTOT  (BATCH*SEQ)   // 8192

// Static scratch: fp16 inputs + fp16 projected Q/K/V (V stored transposed).
__device__ __half g_xh[(size_t)MTOT * HID];          // fp16(X)
__device__ __half g_wth[(size_t)3 * HID * HID];      // fp16(W^T), [n][k], 3 stacked
__device__ __half g_qh[(size_t)MTOT * HID];          // Q  [B,nh,S,hd]
__device__ __half g_kh[(size_t)MTOT * HID];          // K  [B,nh,S,hd]
__device__ __half g_vth[(size_t)MTOT * HID];         // V^T [B,nh,hd,S]

__device__ __forceinline__ float ex2(float x) {
    float r;
    asm("ex2.approx.ftz.f32 %0, %1;" : "=f"(r) : "f"(x));
    return r;
}

__device__ __forceinline__ void mma_f16(float c[4], const uint32_t a[4],
                                        const uint32_t b[2]) {
    asm volatile(
        "mma.sync.aligned.m16n8k16.row.col.f32.f16.f16.f32 "
        "{%0,%1,%2,%3}, {%4,%5,%6,%7}, {%8,%9}, {%0,%1,%2,%3};\n"
        : "+f"(c[0]), "+f"(c[1]), "+f"(c[2]), "+f"(c[3])
        : "r"(a[0]), "r"(a[1]), "r"(a[2]), "r"(a[3]), "r"(b[0]), "r"(b[1]));
}

__device__ __forceinline__ void ldsm_x4(uint32_t r[4], uint32_t addr) {
    asm volatile("ldmatrix.sync.aligned.m8n8.x4.shared.b16 {%0,%1,%2,%3}, [%4];"
                 : "=r"(r[0]), "=r"(r[1]), "=r"(r[2]), "=r"(r[3]) : "r"(addr));
}

__device__ __forceinline__ void cp16(uint32_t smem_addr, const void* gptr) {
    asm volatile("cp.async.ca.shared.global [%0], [%1], 16;\n"
                 :: "r"(smem_addr), "l"(gptr));
}
__device__ __forceinline__ void cp_commit() {
    asm volatile("cp.async.commit_group;\n");
}
__device__ __forceinline__ void cp_wait0() {
    asm volatile("cp.async.wait_group 0;\n");
}
__device__ __forceinline__ void cp_wait1() {
    asm volatile("cp.async.wait_group 1;\n");
}

// ---------------------------------------------------------------------------
// Prologue 1: X fp32 -> fp16 (elementwise).
// ---------------------------------------------------------------------------
__global__ __launch_bounds__(256) void conv_x(const float* __restrict__ X,
                                              __half* __restrict__ xh)
{
    const int n4 = MTOT * HID / 4;
    const int stride = gridDim.x * 256;
    for (int i = blockIdx.x * 256 + threadIdx.x; i < n4; i += stride) {
        float4 v = ((const float4*)X)[i];
        __half2 lo = __floats2half2_rn(v.x, v.y);
        __half2 hi = __floats2half2_rn(v.z, v.w);
        ((uint2*)xh)[i] = make_uint2(*(uint32_t*)&lo, *(uint32_t*)&hi);
    }
}

// ---------------------------------------------------------------------------
// Prologue 2: W fp32 [k][n] -> fp16 transposed [n][k].
// ---------------------------------------------------------------------------
__global__ __launch_bounds__(256) void transpose_w(
    const float* __restrict__ Wq, const float* __restrict__ Wk,
    const float* __restrict__ Wv, __half* __restrict__ wt)
{
    __shared__ float tile[32][33];
    const float* W = (blockIdx.z == 0) ? Wq : (blockIdx.z == 1) ? Wk : Wv;
    __half* dst = wt + (size_t)blockIdx.z * HID * HID;

    int tx = threadIdx.x & 31, ty = threadIdx.x >> 5;
    int x = blockIdx.x * 32 + tx;
    int y = blockIdx.y * 32 + ty;
    #pragma unroll
    for (int j = 0; j < 4; j++)
        tile[ty + 8 * j][tx] = W[(size_t)(y + 8 * j) * HID + x];
    __syncthreads();
    int x2 = blockIdx.y * 32 + tx;
    int y2 = blockIdx.x * 32 + ty;
    #pragma unroll
    for (int j = 0; j < 4; j++)
        dst[(size_t)(y2 + 8 * j) * HID + x2] = __float2half_rn(tile[tx][ty + 8 * j]);
}

// ---------------------------------------------------------------------------
// FP16 QKV projection: BK=64 (16 k-iters, half the barriers) + ldmatrix.x4
// fragment loads (6 LDSM vs 24 LDS.32 per k16 chunk). 3-stage cp.async ring.
// A tile [128 rows][TW=36 words], B tile (W^T) [128 rows][36 words]; LDSM
// 8-row phases hit banks {0,20,8,28,16,4,24,12}x4 = all 32, conflict-free.
// Epilogue unchanged: Q,K fp16 [B,nh,S,hd]; V fp16 transposed [B,nh,hd,S].
// ---------------------------------------------------------------------------
#define BM 128
#define BN 128
#define BK 64
#define TW 36                                // words per row (32 data + 4 pad)
#define G_A_WORDS (BM * TW)                  // 4608
#define G_STAGE   (2 * G_A_WORDS)            // 9216 words = 36864 B
#define GEMM_SMEM_BYTES (3 * G_STAGE * 4)    // 110592 B

__global__ __launch_bounds__(256, 2) void qkv_gemm_f16(
    const __half* __restrict__ X,
    const __half* __restrict__ Wt,
    const float* __restrict__ bq, const float* __restrict__ bk,
    const float* __restrict__ bv)
{
    extern __shared__ uint32_t smg[];
    const int z = blockIdx.z;
    const __half* W = Wt + (size_t)z * HID * HID;
    const float* bias = (z == 0) ? bq : (z == 1) ? bk : bv;

    const int tid  = threadIdx.x;
    const int lane = tid & 31;
    const int w    = tid >> 5;
    const int wm   = w >> 2;                 // 0..1
    const int wn   = w & 3;                  // 0..3
    const int m0   = blockIdx.y * BM;
    const int n0   = blockIdx.x * BN;
    const int lg   = lane >> 2;
    const int lt   = lane & 3;
    const int am0  = wm * 64;
    const int bn0  = wn * 32;

    uint32_t smem_base;
    { void* p = smg; smem_base = (uint32_t)__cvta_generic_to_shared(p); }

    // ldmatrix lane-address components
    const int g  = lane >> 3;                // 0..3 (matrix group)
    const int lr = lane & 7;
    // A x4 = {rows 0-7 kLo, rows 8-15 kLo, rows 0-7 kHi, rows 8-15 kHi}
    const uint32_t aoff = ((am0 + (g & 1) * 8 + lr) * TW + (g >> 1) * 4) * 4;
    // B x4 = {n 0-7 kLo, n 0-7 kHi, n 8-15 kLo, n 8-15 kHi}
    const uint32_t boff = (G_A_WORDS + (bn0 + (g >> 1) * 8 + lr) * TW + (g & 1) * 4) * 4;

    // cp.async slices: A 1024 chunks + B 1024 chunks over 256 threads
    auto issue = [&](int stage, int k0) {
        uint32_t ab = smem_base + stage * G_STAGE * 4;
        #pragma unroll
        for (int p = 0; p < 8; p++) {
            int idx = tid + p * 256;          // 0..2047
            int r   = (idx >> 3) & 127;
            int c8  = (idx & 7) * 8;          // half offset 0..56
            if (idx < 1024)
                cp16(ab + (r * TW + c8 / 2) * 4,
                     X + (size_t)(m0 + r) * HID + k0 + c8);
            else
                cp16(ab + (G_A_WORDS + r * TW + c8 / 2) * 4,
                     W + (size_t)(n0 + r) * HID + k0 + c8);
        }
        cp_commit();
    };

    float c[4][4][4];
    #pragma unroll
    for (int mt = 0; mt < 4; mt++)
        #pragma unroll
        for (int nt = 0; nt < 4; nt++)
            #pragma unroll
            for (int i = 0; i < 4; i++) c[mt][nt][i] = 0.0f;

    issue(0, 0);
    issue(1, BK);

    const int NITER = HID / BK;               // 16
    int st = 0, st2 = 2;

    for (int ki = 0; ki < NITER; ki++) {
        if (ki == NITER - 1) cp_wait0(); else cp_wait1();
        __syncthreads();
        if (ki + 2 < NITER) issue(st2, (ki + 2) * BK);

        const uint32_t stb = smem_base + st * G_STAGE * 4;

        #pragma unroll
        for (int kc = 0; kc < 4; kc++) {      // 4 k16 chunks
            const uint32_t kadd = kc * 8 * 4; // word offset *4 bytes
            uint32_t af[4][4], bfr[2][4];
            #pragma unroll
            for (int mt = 0; mt < 4; mt++)
                ldsm_x4(af[mt], stb + aoff + mt * 16 * TW * 4 + kadd);
            #pragma unroll
            for (int np = 0; np < 2; np++)
                ldsm_x4(bfr[np], stb + boff + np * 16 * TW * 4 + kadd);
            #pragma unroll
            for (int mt = 0; mt < 4; mt++)
                #pragma unroll
                for (int nt = 0; nt < 4; nt++) {
                    uint32_t bb[2] = { bfr[nt >> 1][(nt & 1) * 2],
                                       bfr[nt >> 1][(nt & 1) * 2 + 1] };
                    mma_f16(c[mt][nt], af[mt], bb);
                }
        }
        st  = (st == 2) ? 0 : st + 1;
        st2 = (st2 == 2) ? 0 : st2 + 1;
    }

    #pragma unroll
    for (int mt = 0; mt < 4; mt++) {
        int m = m0 + am0 + mt * 16 + lg;
        #pragma unroll
        for (int nt = 0; nt < 4; nt++) {
            int n = n0 + bn0 + nt * 8 + lt * 2;
            float b0 = bias[n], b1 = bias[n + 1];
            int h = n >> 6, d = n & (HD - 1);
            #pragma unroll
            for (int half_ = 0; half_ < 2; half_++) {
                int mm = m + half_ * 8;
                int bb = mm >> 10, s = mm & (SEQ - 1);
                float v0 = c[mt][nt][half_ * 2]     + b0;
                float v1 = c[mt][nt][half_ * 2 + 1] + b1;
                size_t bh = (size_t)bb * NH + h;
                if (z == 2) {
                    g_vth[(bh * HD + d)     * SEQ + s] = __float2half_rn(v0);
                    g_vth[(bh * HD + d + 1) * SEQ + s] = __float2half_rn(v1);
                } else {
                    __half2 hv = __floats2half2_rn(v0, v1);
                    __half* out = (z == 0) ? g_qh : g_kh;
                    *(uint32_t*)(out + (bh * SEQ + s) * HD + d) = *(uint32_t*)&hv;
                }
            }
        }
    }
}

// ---------------------------------------------------------------------------
// FP16 flash attention (unchanged from R16): 32 q-rows per warp, 128 threads,
// __launch_bounds__(128,3), cp.async 3-stage K/V pipeline.
// ---------------------------------------------------------------------------
#define KW2 36
#define VW2 36
#define PW2 36
#define SMEM_K  (64 * KW2)
#define SMEM_V  (64 * VW2)
#define A_STAGE (SMEM_K + SMEM_V)
#define SMEM_PW (32 * PW2)
#define ATTN_SMEM_BYTES ((3 * A_STAGE + 4 * SMEM_PW) * 4)   // 73728 B

__global__ __launch_bounds__(128, 3) void attn_tc(float* __restrict__ out)
{
    extern __shared__ uint32_t sm[];
    const int tid  = threadIdx.x;
    const int lane = tid & 31;
    const int w    = tid >> 5;
    const int lg   = lane >> 2;
    const int lt   = lane & 3;
    uint32_t* Ph = sm + 3 * A_STAGE + w * SMEM_PW;

    const int qt = blockIdx.x;
    const int h  = blockIdx.y;
    const int bb = blockIdx.z;
    const size_t bh = (size_t)bb * NH + h;
    const __half* Qg = g_qh + (bh * SEQ + qt * 128 + w * 32) * HD;
    const __half* Kg = g_kh + bh * SEQ * HD;
    const __half* Vg = g_vth + bh * HD * SEQ;

    const int qblk = qt * 2 + (w >> 1);

    uint32_t smem_base;
    { void* p = sm; smem_base = (uint32_t)__cvta_generic_to_shared(p); }

    auto issueKV = [&](int stage, int tile) {
        uint32_t kb2 = smem_base + stage * A_STAGE * 4;
        uint32_t vb2 = kb2 + SMEM_K * 4;
        #pragma unroll
        for (int i = 0; i < 8; i++) {
            int idx = tid + i * 128;
            if (idx < 512) {
                int r = idx >> 3, c8 = (idx & 7) * 8;
                cp16(kb2 + (r * KW2 + c8 / 2) * 4,
                     Kg + ((size_t)tile * 64 + r) * HD + c8);
            } else {
                int j = idx - 512;
                int r = j >> 3, c8 = (j & 7) * 8;
                cp16(vb2 + (r * VW2 + c8 / 2) * 4,
                     Vg + (size_t)r * SEQ + tile * 64 + c8);
            }
        }
        cp_commit();
    };

    uint32_t qf[2][4][4];
    #pragma unroll
    for (int mt = 0; mt < 2; mt++)
        #pragma unroll
        for (int kc = 0; kc < 4; kc++)
            #pragma unroll
            for (int e = 0; e < 4; e++) {
                int row = mt * 16 + lg + (e & 1) * 8;
                int col = kc * 16 + 2 * lt + (e >> 1) * 8;
                qf[mt][kc][e] = *(const uint32_t*)(Qg + row * HD + col);
            }

    float o[2][8][4];
    #pragma unroll
    for (int mt = 0; mt < 2; mt++)
        #pragma unroll
        for (int nt = 0; nt < 8; nt++)
            #pragma unroll
            for (int e = 0; e < 4; e++) o[mt][nt][e] = 0.0f;
    float lsum[2][2] = {{0.0f, 0.0f}, {0.0f, 0.0f}};

    const float C1 = 0.18033688f;
    const int NT = SEQ / 64;

    issueKV(0, 0);
    issueKV(1, 1);

    int st = 0, st2 = 2;

    for (int kt64 = 0; kt64 < NT; kt64++) {
        if (kt64 == NT - 1) cp_wait0(); else cp_wait1();
        __syncthreads();
        if (kt64 + 2 < NT) issueKV(st2, kt64 + 2);

        const uint32_t* Ks = sm + st * A_STAGE;
        const uint32_t* Vs = Ks + SMEM_K;
        const float pen2 = (qblk != kt64) ? 0.72134752f : 0.0f;

        #pragma unroll
        for (int half_ = 0; half_ < 2; half_++) {
            float sc[2][4][4];
            #pragma unroll
            for (int mt = 0; mt < 2; mt++)
                #pragma unroll
                for (int j = 0; j < 4; j++)
                    #pragma unroll
                    for (int e = 0; e < 4; e++) sc[mt][j][e] = 0.0f;

            #pragma unroll
            for (int kc = 0; kc < 4; kc++) {
                const int kw = kc * 8;
                #pragma unroll
                for (int j = 0; j < 4; j++) {
                    int nt = half_ * 4 + j;
                    uint32_t bfr[2];
                    bfr[0] = Ks[(nt * 8 + lg) * KW2 + kw + lt];
                    bfr[1] = Ks[(nt * 8 + lg) * KW2 + kw + lt + 4];
                    mma_f16(sc[0][j], qf[0][kc], bfr);
                    mma_f16(sc[1][j], qf[1][kc], bfr);
                }
            }

            #pragma unroll
            for (int mt = 0; mt < 2; mt++)
                #pragma unroll
                for (int j = 0; j < 4; j++) {
                    int nt = half_ * 4 + j;
                    float p0 = ex2(fmaf(sc[mt][j][0], C1, -pen2));
                    float p1 = ex2(fmaf(sc[mt][j][1], C1, -pen2));
                    float p2 = ex2(fmaf(sc[mt][j][2], C1, -pen2));
                    float p3 = ex2(fmaf(sc[mt][j][3], C1, -pen2));
                    lsum[mt][0] += p0 + p1;
                    lsum[mt][1] += p2 + p3;
                    __half2 hA = __floats2half2_rn(p0, p1);
                    __half2 hB = __floats2half2_rn(p2, p3);
                    Ph[(mt * 16 + lg) * PW2 + nt * 4 + lt]     = *(uint32_t*)&hA;
                    Ph[(mt * 16 + lg + 8) * PW2 + nt * 4 + lt] = *(uint32_t*)&hB;
                }
        }
        __syncwarp();

        #pragma unroll
        for (int kc = 0; kc < 4; kc++) {
            const int kw = kc * 8;
            uint32_t ap[2][4];
            #pragma unroll
            for (int mt = 0; mt < 2; mt++) {
                ap[mt][0] = Ph[(mt * 16 + lg) * PW2 + kw + lt];
                ap[mt][1] = Ph[(mt * 16 + lg + 8) * PW2 + kw + lt];
                ap[mt][2] = Ph[(mt * 16 + lg) * PW2 + kw + lt + 4];
                ap[mt][3] = Ph[(mt * 16 + lg + 8) * PW2 + kw + lt + 4];
            }
            #pragma unroll
            for (int nt = 0; nt < 8; nt++) {
                uint32_t bfr[2];
                bfr[0] = Vs[(nt * 8 + lg) * VW2 + kw + lt];
                bfr[1] = Vs[(nt * 8 + lg) * VW2 + kw + lt + 4];
                mma_f16(o[0][nt], ap[0], bfr);
                mma_f16(o[1][nt], ap[1], bfr);
            }
        }
        st  = (st == 2) ? 0 : st + 1;
        st2 = (st2 == 2) ? 0 : st2 + 1;
    }

    #pragma unroll
    for (int mt = 0; mt < 2; mt++)
        #pragma unroll
        for (int i = 0; i < 2; i++) {
            lsum[mt][i] += __shfl_xor_sync(0xFFFFFFFFu, lsum[mt][i], 1);
            lsum[mt][i] += __shfl_xor_sync(0xFFFFFFFFu, lsum[mt][i], 2);
        }

    #pragma unroll
    for (int mt = 0; mt < 2; mt++) {
        const float inv0 = 1.0f / lsum[mt][0];
        const float inv1 = 1.0f / lsum[mt][1];
        const int qbase = qt * 128 + w * 32 + mt * 16;
        #pragma unroll
        for (int nt = 0; nt < 8; nt++) {
            int d = h * HD + nt * 8 + 2 * lt;
            {
                size_t off = ((size_t)bb * SEQ + qbase + lg) * HID + d;
                *(float2*)(out + off) =
                    make_float2(o[mt][nt][0] * inv0, o[mt][nt][1] * inv0);
            }
            {
                size_t off = ((size_t)bb * SEQ + qbase + lg + 8) * HID + d;
                *(float2*)(out + off) =
                    make_float2(o[mt][nt][2] * inv1, o[mt][nt][3] * inv1);
            }
        }
    }
}

// ---------------------------------------------------------------------------
extern "C" void kernel_launch(void* const* d_in, const int* in_sizes, int n_in,
                              void* d_out, int out_size)
{
    const float* X  = (const float*)d_in[0];
    const float* Wq = (const float*)d_in[1];
    const float* bq = (const float*)d_in[2];
    const float* Wk = (const float*)d_in[3];
    const float* bk = (const float*)d_in[4];
    const float* Wv = (const float*)d_in[5];
    const float* bv = (const float*)d_in[6];

    cudaFuncSetAttribute(qkv_gemm_f16, cudaFuncAttributeMaxDynamicSharedMemorySize,
                         GEMM_SMEM_BYTES);
    cudaFuncSetAttribute(attn_tc, cudaFuncAttributeMaxDynamicSharedMemorySize,
                         ATTN_SMEM_BYTES);

    __half *xh, *wth;
    cudaGetSymbolAddress((void**)&xh, g_xh);
    cudaGetSymbolAddress((void**)&wth, g_wth);

    conv_x<<<512, 256>>>(X, xh);
    transpose_w<<<dim3(32, 32, 3), 256>>>(Wq, Wk, Wv, wth);

    dim3 g1(HID / BN, MTOT / BM, 3);
    qkv_gemm_f16<<<g1, 256, GEMM_SMEM_BYTES>>>(xh, wth, bq, bk, bv);

    dim3 g2(SEQ / 128, NH, BATCH);
    attn_tc<<<g2, 128, ATTN_SMEM_BYTES>>>((float*)d_out);
}